// round 3
// baseline (speedup 1.0000x reference)
#include <cuda_runtime.h>
#include <math.h>

#define BATCH 2
#define L 192
#define D 384
#define H 8
#define DH 48
#define EPS 1e-5f
#define SCALE 0.14433756729740643f   // 1/sqrt(48)

// ---------------- scratch (device globals: no allocations allowed) ----------
__device__ float g_xn[BATCH * L * D];
__device__ float g_v[BATCH * L * D];
__device__ float g_dots[BATCH * H * L * L];
__device__ float g_ctx[BATCH * L * D];

// ---------------- LayerNorm -------------------------------------------------
__global__ void ln_kernel(const float* __restrict__ x,
                          const float* __restrict__ gamma,
                          const float* __restrict__ beta) {
    int row = blockIdx.x;                 // b*L + l
    const float* xr = x + (size_t)row * D;
    float* o = g_xn + (size_t)row * D;
    int t = threadIdx.x;                  // 128 threads
    float v0 = xr[t], v1 = xr[t + 128], v2 = xr[t + 256];
    float s = v0 + v1 + v2;
    float sq = v0 * v0 + v1 * v1 + v2 * v2;
    #pragma unroll
    for (int off = 16; off; off >>= 1) {
        s  += __shfl_xor_sync(0xffffffffu, s,  off);
        sq += __shfl_xor_sync(0xffffffffu, sq, off);
    }
    __shared__ float ss[4], ssq[4];
    int w = t >> 5;
    if ((t & 31) == 0) { ss[w] = s; ssq[w] = sq; }
    __syncthreads();
    __shared__ float smu, srstd;
    if (t == 0) {
        float a = ss[0] + ss[1] + ss[2] + ss[3];
        float b2 = ssq[0] + ssq[1] + ssq[2] + ssq[3];
        float mu = a * (1.0f / D);
        float var = b2 * (1.0f / D) - mu * mu;
        smu = mu;
        srstd = rsqrtf(var + EPS);
    }
    __syncthreads();
    float mu = smu, rstd = srstd;
    o[t]       = (v0 - mu) * rstd * gamma[t]       + beta[t];
    o[t + 128] = (v1 - mu) * rstd * gamma[t + 128] + beta[t + 128];
    o[t + 256] = (v2 - mu) * rstd * gamma[t + 256] + beta[t + 256];
}

// ---------------- generic 384x384x384 GEMM body (M=N=K=384) -----------------
// grid (6,6), 256 threads, 64x64 tile, 4x4 per thread, KT=16
template <bool HAS_BIAS>
__device__ __forceinline__ void gemm384_body(
    const float* __restrict__ A, const float* __restrict__ Bm,
    const float* __restrict__ bias, float* __restrict__ C) {
    __shared__ float sA[16][64];
    __shared__ float sB[16][64];
    int bm = blockIdx.y * 64, bn = blockIdx.x * 64;
    int t = threadIdx.x;
    int tx = t & 15, ty = t >> 4;         // 16 col groups x 16 row groups
    float acc[4][4] = {};
    for (int k0 = 0; k0 < 384; k0 += 16) {
        {   // A tile 64x16 -> transposed smem
            int m = t >> 2, f = t & 3;
            float4 av = *(const float4*)(A + (size_t)(bm + m) * 384 + k0 + f * 4);
            sA[f * 4 + 0][m] = av.x; sA[f * 4 + 1][m] = av.y;
            sA[f * 4 + 2][m] = av.z; sA[f * 4 + 3][m] = av.w;
        }
        {   // B tile 16x64
            int kk = t >> 4, n4 = t & 15;
            *(float4*)&sB[kk][n4 * 4] =
                *(const float4*)(Bm + (size_t)(k0 + kk) * 384 + bn + n4 * 4);
        }
        __syncthreads();
        #pragma unroll
        for (int kk = 0; kk < 16; ++kk) {
            float4 a4 = *(const float4*)&sA[kk][ty * 4];
            float4 b4 = *(const float4*)&sB[kk][tx * 4];
            float av[4] = {a4.x, a4.y, a4.z, a4.w};
            float bv[4] = {b4.x, b4.y, b4.z, b4.w};
            #pragma unroll
            for (int i = 0; i < 4; ++i)
                #pragma unroll
                for (int j = 0; j < 4; ++j)
                    acc[i][j] += av[i] * bv[j];
        }
        __syncthreads();
    }
    #pragma unroll
    for (int i = 0; i < 4; ++i)
        #pragma unroll
        for (int j = 0; j < 4; ++j) {
            float v = acc[i][j];
            if (HAS_BIAS) v += bias[bn + tx * 4 + j];
            C[(size_t)(bm + ty * 4 + i) * 384 + bn + tx * 4 + j] = v;
        }
}

// v = xn @ w_v : reads g_xn (device global), writes g_v (device global)
__global__ __launch_bounds__(256) void vproj_kernel(const float* __restrict__ wv) {
    gemm384_body<false>(g_xn, wv, nullptr, g_v);
}

// out = ctx @ w_o + b_o : reads g_ctx, writes harness output
__global__ __launch_bounds__(256) void oproj_kernel(const float* __restrict__ wo,
                                                    const float* __restrict__ bo,
                                                    float* __restrict__ out) {
    gemm384_body<true>(g_ctx, wo, bo, out);
}

// ---------------- main: per-diagonal dual GEMM + per-head dot ---------------
// grid (3 mtiles, 8 heads, B*L (b,r)), 192 threads
// block tile: 64 rows x 48 cols (one head), K=384
__global__ __launch_bounds__(192) void diag_kernel(
    const float* __restrict__ uq, const float* __restrict__ uk) {
    int bz = blockIdx.z;
    int b = bz / L, r = bz % L;
    int head = blockIdx.y;
    int m0 = blockIdx.x * 64;
    int M = L - r;
    if (m0 >= M) return;
    int rows = M - m0; if (rows > 64) rows = 64;

    const float* Aq = g_xn + (size_t)(b * L + r + m0) * D;   // q rows: i = r+m0+m
    const float* Ak = g_xn + (size_t)(b * L + m0) * D;       // k rows: j = m0+m
    const float* Bq = uq + (size_t)(L - 1 - r) * D * D + head * DH;
    const float* Bk = uk + (size_t)r * D * D + head * DH;

    __shared__ float sXq[16][64];
    __shared__ float sXk[16][64];
    __shared__ float sUq[16][48];
    __shared__ float sUk[16][48];
    __shared__ float sRed[64][12];

    int t = threadIdx.x;
    int tx = t % 12, ty = t / 12;   // 12 col groups (4 cols), 16 row groups (4 rows)
    float cq[4][4] = {}, ck[4][4] = {};

    for (int k0 = 0; k0 < D; k0 += 16) {
        for (int idx = t; idx < 256; idx += 192) {
            int m = idx >> 2, f = idx & 3;
            float4 q4 = make_float4(0.f, 0.f, 0.f, 0.f);
            float4 k4 = make_float4(0.f, 0.f, 0.f, 0.f);
            if (m < rows) {
                q4 = *(const float4*)(Aq + (size_t)m * D + k0 + f * 4);
                k4 = *(const float4*)(Ak + (size_t)m * D + k0 + f * 4);
            }
            sXq[f * 4 + 0][m] = q4.x; sXq[f * 4 + 1][m] = q4.y;
            sXq[f * 4 + 2][m] = q4.z; sXq[f * 4 + 3][m] = q4.w;
            sXk[f * 4 + 0][m] = k4.x; sXk[f * 4 + 1][m] = k4.y;
            sXk[f * 4 + 2][m] = k4.z; sXk[f * 4 + 3][m] = k4.w;
        }
        {
            int kk = t / 12, n4 = t % 12;    // 16*12 = 192 exactly
            *(float4*)&sUq[kk][n4 * 4] =
                *(const float4*)(Bq + (size_t)(k0 + kk) * D + n4 * 4);
            *(float4*)&sUk[kk][n4 * 4] =
                *(const float4*)(Bk + (size_t)(k0 + kk) * D + n4 * 4);
        }
        __syncthreads();
        #pragma unroll
        for (int kk = 0; kk < 16; ++kk) {
            float4 aq = *(const float4*)&sXq[kk][ty * 4];
            float4 ak = *(const float4*)&sXk[kk][ty * 4];
            float4 bq = *(const float4*)&sUq[kk][tx * 4];
            float4 bk = *(const float4*)&sUk[kk][tx * 4];
            float aqv[4] = {aq.x, aq.y, aq.z, aq.w};
            float akv[4] = {ak.x, ak.y, ak.z, ak.w};
            float bqv[4] = {bq.x, bq.y, bq.z, bq.w};
            float bkv[4] = {bk.x, bk.y, bk.z, bk.w};
            #pragma unroll
            for (int i = 0; i < 4; ++i)
                #pragma unroll
                for (int j = 0; j < 4; ++j) {
                    cq[i][j] += aqv[i] * bqv[j];
                    ck[i][j] += akv[i] * bkv[j];
                }
        }
        __syncthreads();
    }

    // pointwise Q*K + reduce across the 12 column groups -> per-row head dot
    #pragma unroll
    for (int i = 0; i < 4; ++i) {
        float s = cq[i][0] * ck[i][0] + cq[i][1] * ck[i][1]
                + cq[i][2] * ck[i][2] + cq[i][3] * ck[i][3];
        sRed[ty * 4 + i][tx] = s;
    }
    __syncthreads();
    if (t < rows) {
        float sum = 0.f;
        #pragma unroll
        for (int xx = 0; xx < 12; ++xx) sum += sRed[t][xx];
        int i = r + m0 + t, j = m0 + t;
        g_dots[((size_t)(b * H + head) * L + i) * L + j] = sum * SCALE;
    }
}

// ---------------- softmax over valid (causal) range + attn @ v --------------
// grid (L, H, B), 192 threads
__global__ __launch_bounds__(192) void softmax_av_kernel() {
    int i = blockIdx.x, h = blockIdx.y, b = blockIdx.z;
    int t = threadIdx.x;
    const float* drow = g_dots + ((size_t)(b * H + h) * L + i) * L;

    __shared__ float sP[192];
    __shared__ float swork[6];
    __shared__ float smax, ssum;
    __shared__ float sAcc[4][48];

    float val = (t <= i) ? drow[t] : -INFINITY;
    float m = val;
    #pragma unroll
    for (int off = 16; off; off >>= 1)
        m = fmaxf(m, __shfl_xor_sync(0xffffffffu, m, off));
    if ((t & 31) == 0) swork[t >> 5] = m;
    __syncthreads();
    if (t == 0) {
        float mm = swork[0];
        #pragma unroll
        for (int k = 1; k < 6; ++k) mm = fmaxf(mm, swork[k]);
        smax = mm;
    }
    __syncthreads();
    float p = (t <= i) ? expf(val - smax) : 0.f;
    sP[t] = p;
    float s = p;
    #pragma unroll
    for (int off = 16; off; off >>= 1)
        s += __shfl_xor_sync(0xffffffffu, s, off);
    if ((t & 31) == 0) swork[t >> 5] = s;
    __syncthreads();
    if (t == 0) {
        float acc = 0.f;
        #pragma unroll
        for (int k = 0; k < 6; ++k) acc += swork[k];
        ssum = acc;
    }
    __syncthreads();
    float inv = 1.0f / ssum;

    // attn @ v for this (b,h,i): 48 outputs, 4-way split over j
    int d = t % 48, q = t / 48;
    float acc = 0.f;
    for (int j = q; j <= i; j += 4)
        acc += sP[j] * g_v[(size_t)(b * L + j) * D + h * DH + d];
    sAcc[q][d] = acc;
    __syncthreads();
    if (t < 48) {
        float o = (sAcc[0][t] + sAcc[1][t] + sAcc[2][t] + sAcc[3][t]) * inv;
        g_ctx[(size_t)(b * L + i) * D + h * DH + t] = o;
    }
}

extern "C" void kernel_launch(void* const* d_in, const int* in_sizes, int n_in,
                              void* d_out, int out_size) {
    const float* x     = (const float*)d_in[0];
    const float* gamma = (const float*)d_in[1];
    const float* beta  = (const float*)d_in[2];
    const float* uq    = (const float*)d_in[3];
    const float* uk    = (const float*)d_in[4];
    const float* wv    = (const float*)d_in[5];
    const float* wo    = (const float*)d_in[6];
    const float* bo    = (const float*)d_in[7];
    float* out = (float*)d_out;
    (void)in_sizes; (void)n_in; (void)out_size;

    // 1) LayerNorm
    ln_kernel<<<BATCH * L, 128>>>(x, gamma, beta);
    // 2) v = xn @ w_v   (M = B*L = 384, N = K = 384)
    vproj_kernel<<<dim3(6, 6), 256>>>(wv);
    // 3) per-diagonal dual GEMM + per-head dots
    diag_kernel<<<dim3(3, H, BATCH * L), 192>>>(uq, uk);
    // 4) causal softmax + attn @ v
    softmax_av_kernel<<<dim3(L, H, BATCH), 192>>>();
    // 5) out = ctx @ w_o + b_o
    oproj_kernel<<<dim3(6, 6), 256>>>(wo, bo, out);
}

// round 6
// speedup vs baseline: 1.5034x; 1.5034x over previous
#include <cuda_runtime.h>
#include <cuda_bf16.h>
#include <math.h>
#include <stdint.h>

#define BATCH 2
#define L 192
#define D 384
#define H 8
#define DH 48
#define EPS 1e-5f
#define SCALE 0.14433756729740643f   // 1/sqrt(48)

// ---------------- scratch (device globals) ----------------------------------
__device__ __align__(16) float g_xn[BATCH * L * D];
__device__ __align__(16) __nv_bfloat16 g_xn_hi[BATCH * L * D];
__device__ __align__(16) __nv_bfloat16 g_xn_lo[BATCH * L * D];
__device__ __align__(16) float g_v[BATCH * L * D];
__device__ __align__(16) float g_dots[BATCH * H * L * L];
__device__ __align__(16) float g_ctx[BATCH * L * D];
// transposed + hi/lo-split u weights: [r][n][k] K-major bf16
__device__ __align__(16) __nv_bfloat16 g_uqt_hi[L * D * D];
__device__ __align__(16) __nv_bfloat16 g_uqt_lo[L * D * D];
__device__ __align__(16) __nv_bfloat16 g_ukt_hi[L * D * D];
__device__ __align__(16) __nv_bfloat16 g_ukt_lo[L * D * D];

// ---------------- helpers -----------------------------------------------------
__device__ __forceinline__ uint32_t smem_u32(const void* p) {
    uint32_t a;
    asm("{ .reg .u64 t; cvta.to.shared.u64 t, %1; cvt.u32.u64 %0, t; }"
        : "=r"(a) : "l"(p));
    return a;
}
__device__ __forceinline__ void ldmx4(uint32_t* f, uint32_t a) {
    asm volatile("ldmatrix.sync.aligned.m8n8.x4.shared.b16 {%0,%1,%2,%3}, [%4];"
                 : "=r"(f[0]), "=r"(f[1]), "=r"(f[2]), "=r"(f[3]) : "r"(a));
}
__device__ __forceinline__ void ldmx2(uint32_t* f, uint32_t a) {
    asm volatile("ldmatrix.sync.aligned.m8n8.x2.shared.b16 {%0,%1}, [%2];"
                 : "=r"(f[0]), "=r"(f[1]) : "r"(a));
}
__device__ __forceinline__ void mma16816(float* c, const uint32_t* a, const uint32_t* b) {
    asm volatile(
        "mma.sync.aligned.m16n8k16.row.col.f32.bf16.bf16.f32 "
        "{%0,%1,%2,%3}, {%4,%5,%6,%7}, {%8,%9}, {%0,%1,%2,%3};"
        : "+f"(c[0]), "+f"(c[1]), "+f"(c[2]), "+f"(c[3])
        : "r"(a[0]), "r"(a[1]), "r"(a[2]), "r"(a[3]), "r"(b[0]), "r"(b[1]));
}

// ---------------- u transpose + hi/lo split ----------------------------------
// in: u[r][k][n] fp32 ; out: t[r][n][k] bf16 hi/lo. grid (12,12,384), block (32,8)
__global__ void tconv_kernel(const float* __restrict__ uq,
                             const float* __restrict__ uk) {
    int z = blockIdx.z;
    int mat = z / L, r = z % L;
    const float* src = (mat ? uk : uq) + (size_t)r * D * D;
    __nv_bfloat16* dhi = (mat ? g_ukt_hi : g_uqt_hi) + (size_t)r * D * D;
    __nv_bfloat16* dlo = (mat ? g_ukt_lo : g_uqt_lo) + (size_t)r * D * D;
    __shared__ float tile[32][33];
    int k0 = blockIdx.y * 32, n0 = blockIdx.x * 32;
    int tx = threadIdx.x, ty = threadIdx.y;
    #pragma unroll
    for (int i = 0; i < 32; i += 8)
        tile[ty + i][tx] = src[(size_t)(k0 + ty + i) * D + n0 + tx];
    __syncthreads();
    #pragma unroll
    for (int i = 0; i < 32; i += 8) {
        float v = tile[tx][ty + i];
        __nv_bfloat16 h = __float2bfloat16(v);
        __nv_bfloat16 lo = __float2bfloat16(v - __bfloat162float(h));
        size_t o = (size_t)(n0 + ty + i) * D + k0 + tx;
        dhi[o] = h;
        dlo[o] = lo;
    }
}

// ---------------- LayerNorm (+ bf16 hi/lo emit) -------------------------------
__global__ void ln_kernel(const float* __restrict__ x,
                          const float* __restrict__ gamma,
                          const float* __restrict__ beta) {
    int row = blockIdx.x;
    const float* xr = x + (size_t)row * D;
    float* o = g_xn + (size_t)row * D;
    __nv_bfloat16* ohi = g_xn_hi + (size_t)row * D;
    __nv_bfloat16* olo = g_xn_lo + (size_t)row * D;
    int t = threadIdx.x;
    float v0 = xr[t], v1 = xr[t + 128], v2 = xr[t + 256];
    float s = v0 + v1 + v2;
    float sq = v0 * v0 + v1 * v1 + v2 * v2;
    #pragma unroll
    for (int off = 16; off; off >>= 1) {
        s  += __shfl_xor_sync(0xffffffffu, s,  off);
        sq += __shfl_xor_sync(0xffffffffu, sq, off);
    }
    __shared__ float ss[4], ssq[4];
    int w = t >> 5;
    if ((t & 31) == 0) { ss[w] = s; ssq[w] = sq; }
    __syncthreads();
    __shared__ float smu, srstd;
    if (t == 0) {
        float a = ss[0] + ss[1] + ss[2] + ss[3];
        float b2 = ssq[0] + ssq[1] + ssq[2] + ssq[3];
        float mu = a * (1.0f / D);
        float var = b2 * (1.0f / D) - mu * mu;
        smu = mu;
        srstd = rsqrtf(var + EPS);
    }
    __syncthreads();
    float mu = smu, rstd = srstd;
    #pragma unroll
    for (int seg = 0; seg < 3; ++seg) {
        int c = t + seg * 128;
        float v = (seg == 0 ? v0 : (seg == 1 ? v1 : v2));
        float on = (v - mu) * rstd * gamma[c] + beta[c];
        o[c] = on;
        __nv_bfloat16 h = __float2bfloat16(on);
        ohi[c] = h;
        olo[c] = __float2bfloat16(on - __bfloat162float(h));
    }
}

// ---------------- generic 384^3 GEMM body ------------------------------------
template <bool HAS_BIAS>
__device__ __forceinline__ void gemm384_body(
    const float* __restrict__ A, const float* __restrict__ Bm,
    const float* __restrict__ bias, float* __restrict__ C) {
    __shared__ float sA[16][64];
    __shared__ float sB[16][64];
    int bm = blockIdx.y * 64, bn = blockIdx.x * 64;
    int t = threadIdx.x;
    int tx = t & 15, ty = t >> 4;
    float acc[4][4] = {};
    for (int k0 = 0; k0 < 384; k0 += 16) {
        {
            int m = t >> 2, f = t & 3;
            float4 av = *(const float4*)(A + (size_t)(bm + m) * 384 + k0 + f * 4);
            sA[f * 4 + 0][m] = av.x; sA[f * 4 + 1][m] = av.y;
            sA[f * 4 + 2][m] = av.z; sA[f * 4 + 3][m] = av.w;
        }
        {
            int kk = t >> 4, n4 = t & 15;
            *(float4*)&sB[kk][n4 * 4] =
                *(const float4*)(Bm + (size_t)(k0 + kk) * 384 + bn + n4 * 4);
        }
        __syncthreads();
        #pragma unroll
        for (int kk = 0; kk < 16; ++kk) {
            float4 a4 = *(const float4*)&sA[kk][ty * 4];
            float4 b4 = *(const float4*)&sB[kk][tx * 4];
            float av[4] = {a4.x, a4.y, a4.z, a4.w};
            float bv[4] = {b4.x, b4.y, b4.z, b4.w};
            #pragma unroll
            for (int i = 0; i < 4; ++i)
                #pragma unroll
                for (int j = 0; j < 4; ++j)
                    acc[i][j] += av[i] * bv[j];
        }
        __syncthreads();
    }
    #pragma unroll
    for (int i = 0; i < 4; ++i)
        #pragma unroll
        for (int j = 0; j < 4; ++j) {
            float v = acc[i][j];
            if (HAS_BIAS) v += bias[bn + tx * 4 + j];
            C[(size_t)(bm + ty * 4 + i) * 384 + bn + tx * 4 + j] = v;
        }
}
__global__ __launch_bounds__(256) void vproj_kernel(const float* __restrict__ wv) {
    gemm384_body<false>(g_xn, wv, nullptr, g_v);
}
__global__ __launch_bounds__(256) void oproj_kernel(const float* __restrict__ wo,
                                                    const float* __restrict__ bo,
                                                    float* __restrict__ out) {
    gemm384_body<true>(g_ctx, wo, bo, out);
}

// ---------------- diagonal dual-GEMM via mma.sync (bf16 hi/lo, K'=1152) ------
// grid (3 mtiles, 192 r), 256 threads = 8 warps (4m x 2n).
// Block: 128 stacked rows (2 batches) x 96 cols (quarter) x K'=1152.
// smem per stage: Aq 128x16, Ak 128x16, Bq 96x16, Bk 96x16 bf16; row pitch 48B.
#define STG      21504
#define OFF_AQ   0
#define OFF_AK   6144
#define OFF_BQ   12288
#define OFF_BK   16896

__global__ __launch_bounds__(256) void diag_mma_kernel() {
    int r = blockIdx.y;
    int mtile = blockIdx.x;
    int M = L - r;
    int rows2 = 2 * M;
    int m0 = mtile * 128;
    if (m0 >= rows2) return;

    __shared__ __align__(16) uint8_t sm[2 * STG];
    uint32_t su = smem_u32(sm);
    int tid = threadIdx.x, lane = tid & 31, wid = tid >> 5;
    int wm = wid & 3, wn = wid >> 2;

    auto issue = [&](int ch, int st, int ncol0) {
        int seg = ch / 24;                 // 0:hi 1:lo 2:hi (A) / 0:hi 1:hi 2:lo (B)
        int k0 = (ch % 24) * 16;
        const __nv_bfloat16* aBase = (seg == 1) ? g_xn_lo : g_xn_hi;
        uint32_t sbase = su + st * STG;
        #pragma unroll
        for (int it = 0; it < 4; ++it) {
            int idx = tid + it * 256;
            if (idx < 512) {
                int tile = idx >> 8, rem = idx & 255, m = rem >> 1, v = rem & 1;
                uint32_t dst = sbase + tile * 6144 + m * 48 + v * 16;
                int g = m0 + m;
                if (g < rows2) {
                    int bb = g >= M;
                    int mm = g - (bb ? M : 0);
                    int xrow = bb * L + (tile == 0 ? r + mm : mm);
                    const __nv_bfloat16* src = aBase + (size_t)xrow * D + k0 + v * 8;
                    asm volatile("cp.async.ca.shared.global [%0], [%1], 16;"
                                 :: "r"(dst), "l"(src));
                } else {
                    asm volatile("cp.async.ca.shared.global [%0], [%1], 16, 0;"
                                 :: "r"(dst), "l"((const __nv_bfloat16*)g_xn_hi));
                }
            } else if (idx < 896) {
                int j = idx - 512;
                int mat = j >= 192;
                int rem = j - (mat ? 192 : 0);
                int n = rem >> 1, v = rem & 1;
                uint32_t dst = sbase + OFF_BQ + mat * 4608 + n * 48 + v * 16;
                int ridx = mat ? r : (L - 1 - r);
                const __nv_bfloat16* base =
                    mat ? ((seg == 2) ? g_ukt_lo : g_ukt_hi)
                        : ((seg == 2) ? g_uqt_lo : g_uqt_hi);
                const __nv_bfloat16* src =
                    base + ((size_t)ridx * D + ncol0 + n) * D + k0 + v * 8;
                asm volatile("cp.async.ca.shared.global [%0], [%1], 16;"
                             :: "r"(dst), "l"(src));
            }
        }
    };

    for (int quarter = 0; quarter < 4; ++quarter) {
        int ncol0 = quarter * 96;
        float accQ[2][6][4] = {}, accK[2][6][4] = {};

        issue(0, 0, ncol0);
        asm volatile("cp.async.commit_group;" ::: "memory");

        for (int ch = 0; ch < 72; ++ch) {
            int st = ch & 1;
            asm volatile("cp.async.wait_group 0;" ::: "memory");
            __syncthreads();
            if (ch + 1 < 72) {
                issue(ch + 1, st ^ 1, ncol0);
                asm volatile("cp.async.commit_group;" ::: "memory");
            }
            uint32_t sb = su + st * STG;
            // A fragments: 2 row-bands of 16 for this warp, both Q and K tiles
            uint32_t aqf[2][4], akf[2][4];
            int arow = (lane & 8) + (lane & 7);
            uint32_t au = (uint32_t)(lane >> 4) * 16;
            #pragma unroll
            for (int band = 0; band < 2; ++band) {
                int rb = wm * 32 + band * 16 + arow;
                ldmx4(aqf[band], sb + OFF_AQ + rb * 48 + au);
                ldmx4(akf[band], sb + OFF_AK + rb * 48 + au);
            }
            int lb = lane & 15;
            int brow = lb & 7;
            uint32_t bu = (uint32_t)(lb >> 3) * 16;
            #pragma unroll
            for (int nt = 0; nt < 6; ++nt) {
                int n0 = wn * 48 + nt * 8 + brow;
                uint32_t bq[2], bk[2];
                ldmx2(bq, sb + OFF_BQ + n0 * 48 + bu);
                ldmx2(bk, sb + OFF_BK + n0 * 48 + bu);
                #pragma unroll
                for (int band = 0; band < 2; ++band) {
                    mma16816(accQ[band][nt], aqf[band], bq);
                    mma16816(accK[band][nt], akf[band], bk);
                }
            }
        }

        // ---- epilogue: rowwise dot over this warp's 48 cols (one head) ------
        #pragma unroll
        for (int band = 0; band < 2; ++band)
            #pragma unroll
            for (int h = 0; h < 2; ++h) {
                float p = 0.f;
                #pragma unroll
                for (int nt = 0; nt < 6; ++nt)
                    p += accQ[band][nt][2 * h] * accK[band][nt][2 * h]
                       + accQ[band][nt][2 * h + 1] * accK[band][nt][2 * h + 1];
                p += __shfl_xor_sync(0xffffffffu, p, 1);
                p += __shfl_xor_sync(0xffffffffu, p, 2);
                if ((lane & 3) == 0) {
                    int row = m0 + wm * 32 + band * 16 + (lane >> 2) + 8 * h;
                    if (row < rows2) {
                        int bb = row >= M;
                        int mm = row - (bb ? M : 0);
                        int i = r + mm, j = mm;
                        int head = quarter * 2 + wn;
                        g_dots[((size_t)(bb * H + head) * L + i) * L + j] = p * SCALE;
                    }
                }
            }
    }
}

// ---------------- softmax + attn @ v -----------------------------------------
__global__ __launch_bounds__(192) void softmax_av_kernel() {
    int i = blockIdx.x, h = blockIdx.y, b = blockIdx.z;
    int t = threadIdx.x;
    const float* drow = g_dots + ((size_t)(b * H + h) * L + i) * L;

    __shared__ float sP[192];
    __shared__ float swork[6];
    __shared__ float smax, ssum;
    __shared__ float sAcc[4][48];

    float val = (t <= i) ? drow[t] : -INFINITY;
    float m = val;
    #pragma unroll
    for (int off = 16; off; off >>= 1)
        m = fmaxf(m, __shfl_xor_sync(0xffffffffu, m, off));
    if ((t & 31) == 0) swork[t >> 5] = m;
    __syncthreads();
    if (t == 0) {
        float mm = swork[0];
        #pragma unroll
        for (int k = 1; k < 6; ++k) mm = fmaxf(mm, swork[k]);
        smax = mm;
    }
    __syncthreads();
    float p = (t <= i) ? expf(val - smax) : 0.f;
    sP[t] = p;
    float s = p;
    #pragma unroll
    for (int off = 16; off; off >>= 1)
        s += __shfl_xor_sync(0xffffffffu, s, off);
    if ((t & 31) == 0) swork[t >> 5] = s;
    __syncthreads();
    if (t == 0) {
        float acc = 0.f;
        #pragma unroll
        for (int k = 0; k < 6; ++k) acc += swork[k];
        ssum = acc;
    }
    __syncthreads();
    float inv = 1.0f / ssum;

    int d = t % 48, q = t / 48;
    float acc = 0.f;
    for (int j = q; j <= i; j += 4)
        acc += sP[j] * g_v[(size_t)(b * L + j) * D + h * DH + d];
    sAcc[q][d] = acc;
    __syncthreads();
    if (t < 48) {
        float o = (sAcc[0][t] + sAcc[1][t] + sAcc[2][t] + sAcc[3][t]) * inv;
        g_ctx[(size_t)(b * L + i) * D + h * DH + t] = o;
    }
}

extern "C" void kernel_launch(void* const* d_in, const int* in_sizes, int n_in,
                              void* d_out, int out_size) {
    const float* x     = (const float*)d_in[0];
    const float* gamma = (const float*)d_in[1];
    const float* beta  = (const float*)d_in[2];
    const float* uq    = (const float*)d_in[3];
    const float* uk    = (const float*)d_in[4];
    const float* wv    = (const float*)d_in[5];
    const float* wo    = (const float*)d_in[6];
    const float* bo    = (const float*)d_in[7];
    float* out = (float*)d_out;
    (void)in_sizes; (void)n_in; (void)out_size;

    // 1) transpose + hi/lo split of u weights (independent of LN)
    tconv_kernel<<<dim3(12, 12, 2 * L), dim3(32, 8)>>>(uq, uk);
    // 2) LayerNorm (+ bf16 hi/lo)
    ln_kernel<<<BATCH * L, 128>>>(x, gamma, beta);
    // 3) v = xn @ w_v
    vproj_kernel<<<dim3(6, 6), 256>>>(wv);
    // 4) per-diagonal dual GEMM + per-head dots (mma.sync bf16 hi/lo)
    diag_mma_kernel<<<dim3(3, L), 256>>>();
    // 5) causal softmax + attn @ v
    softmax_av_kernel<<<dim3(L, H, BATCH), 192>>>();
    // 6) out = ctx @ w_o + b_o
    oproj_kernel<<<dim3(6, 6), 256>>>(wo, bo, out);
}

// round 7
// speedup vs baseline: 1.8338x; 1.2198x over previous
#include <cuda_runtime.h>
#include <cuda_bf16.h>
#include <math.h>
#include <stdint.h>

#define BATCH 2
#define L 192
#define D 384
#define H 8
#define DH 48
#define EPS 1e-5f
#define SCALE 0.14433756729740643f   // 1/sqrt(48)

// ---------------- scratch (device globals) ----------------------------------
__device__ __align__(16) float g_xn[BATCH * L * D];
__device__ __align__(16) __nv_bfloat16 g_xn_hi[BATCH * L * D];
__device__ __align__(16) __nv_bfloat16 g_xn_lo[BATCH * L * D];
__device__ __align__(16) float g_v[BATCH * L * D];
__device__ __align__(16) float g_dots[BATCH * H * L * L];
__device__ __align__(16) float g_ctx[BATCH * L * D];
// transposed + hi/lo-split u weights: [r][n][k] K-major bf16
__device__ __align__(16) __nv_bfloat16 g_uqt_hi[L * D * D];
__device__ __align__(16) __nv_bfloat16 g_uqt_lo[L * D * D];
__device__ __align__(16) __nv_bfloat16 g_ukt_hi[L * D * D];
__device__ __align__(16) __nv_bfloat16 g_ukt_lo[L * D * D];

// ---------------- helpers -----------------------------------------------------
__device__ __forceinline__ uint32_t smem_u32(const void* p) {
    uint32_t a;
    asm("{ .reg .u64 t; cvta.to.shared.u64 t, %1; cvt.u32.u64 %0, t; }"
        : "=r"(a) : "l"(p));
    return a;
}
__device__ __forceinline__ void ldmx4(uint32_t* f, uint32_t a) {
    asm volatile("ldmatrix.sync.aligned.m8n8.x4.shared.b16 {%0,%1,%2,%3}, [%4];"
                 : "=r"(f[0]), "=r"(f[1]), "=r"(f[2]), "=r"(f[3]) : "r"(a));
}
__device__ __forceinline__ void ldmx2(uint32_t* f, uint32_t a) {
    asm volatile("ldmatrix.sync.aligned.m8n8.x2.shared.b16 {%0,%1}, [%2];"
                 : "=r"(f[0]), "=r"(f[1]) : "r"(a));
}
__device__ __forceinline__ void mma16816(float* c, const uint32_t* a, const uint32_t* b) {
    asm volatile(
        "mma.sync.aligned.m16n8k16.row.col.f32.bf16.bf16.f32 "
        "{%0,%1,%2,%3}, {%4,%5,%6,%7}, {%8,%9}, {%0,%1,%2,%3};"
        : "+f"(c[0]), "+f"(c[1]), "+f"(c[2]), "+f"(c[3])
        : "r"(a[0]), "r"(a[1]), "r"(a[2]), "r"(a[3]), "r"(b[0]), "r"(b[1]));
}
#define CP16(dst, src) \
    asm volatile("cp.async.cg.shared.global [%0], [%1], 16;" :: "r"(dst), "l"(src))
#define CP16Z(dst) \
    asm volatile("cp.async.cg.shared.global [%0], [%1], 16, 0;" \
                 :: "r"(dst), "l"((const void*)g_xn_hi))
#define CP_COMMIT() asm volatile("cp.async.commit_group;" ::: "memory")
#define CP_WAIT1()  asm volatile("cp.async.wait_group 1;" ::: "memory")

// ---------------- u transpose + hi/lo split ----------------------------------
// in: u[r][k][n] fp32 ; out: t[r][n][k] bf16 hi/lo. grid (12,6,384), block (32,8)
__global__ void tconv_kernel(const float* __restrict__ uq,
                             const float* __restrict__ uk) {
    int z = blockIdx.z;
    int mat = z / L, r = z % L;
    const float* src = (mat ? uk : uq) + (size_t)r * D * D;
    __nv_bfloat16* dhi = (mat ? g_ukt_hi : g_uqt_hi) + (size_t)r * D * D;
    __nv_bfloat16* dlo = (mat ? g_ukt_lo : g_uqt_lo) + (size_t)r * D * D;
    __shared__ float tile[64][33];
    int k0 = blockIdx.y * 64, n0 = blockIdx.x * 32;
    int tx = threadIdx.x, ty = threadIdx.y;
    #pragma unroll
    for (int i = 0; i < 8; ++i)
        tile[ty + 8 * i][tx] = src[(size_t)(k0 + ty + 8 * i) * D + n0 + tx];
    __syncthreads();
    #pragma unroll
    for (int i = 0; i < 4; ++i) {
        int n = ty + 8 * i;
        float v0 = tile[2 * tx][n], v1 = tile[2 * tx + 1][n];
        __nv_bfloat16 h0 = __float2bfloat16(v0);
        __nv_bfloat16 h1 = __float2bfloat16(v1);
        __nv_bfloat16 l0 = __float2bfloat16(v0 - __bfloat162float(h0));
        __nv_bfloat16 l1 = __float2bfloat16(v1 - __bfloat162float(h1));
        size_t o = (size_t)(n0 + n) * D + k0 + 2 * tx;
        *(__nv_bfloat162*)(dhi + o) = __nv_bfloat162(h0, h1);
        *(__nv_bfloat162*)(dlo + o) = __nv_bfloat162(l0, l1);
    }
}

// ---------------- LayerNorm (+ bf16 hi/lo emit) -------------------------------
__global__ void ln_kernel(const float* __restrict__ x,
                          const float* __restrict__ gamma,
                          const float* __restrict__ beta) {
    int row = blockIdx.x;
    const float* xr = x + (size_t)row * D;
    float* o = g_xn + (size_t)row * D;
    __nv_bfloat16* ohi = g_xn_hi + (size_t)row * D;
    __nv_bfloat16* olo = g_xn_lo + (size_t)row * D;
    int t = threadIdx.x;
    float v0 = xr[t], v1 = xr[t + 128], v2 = xr[t + 256];
    float s = v0 + v1 + v2;
    float sq = v0 * v0 + v1 * v1 + v2 * v2;
    #pragma unroll
    for (int off = 16; off; off >>= 1) {
        s  += __shfl_xor_sync(0xffffffffu, s,  off);
        sq += __shfl_xor_sync(0xffffffffu, sq, off);
    }
    __shared__ float ss[4], ssq[4];
    int w = t >> 5;
    if ((t & 31) == 0) { ss[w] = s; ssq[w] = sq; }
    __syncthreads();
    __shared__ float smu, srstd;
    if (t == 0) {
        float a = ss[0] + ss[1] + ss[2] + ss[3];
        float b2 = ssq[0] + ssq[1] + ssq[2] + ssq[3];
        float mu = a * (1.0f / D);
        float var = b2 * (1.0f / D) - mu * mu;
        smu = mu;
        srstd = rsqrtf(var + EPS);
    }
    __syncthreads();
    float mu = smu, rstd = srstd;
    #pragma unroll
    for (int seg = 0; seg < 3; ++seg) {
        int c = t + seg * 128;
        float v = (seg == 0 ? v0 : (seg == 1 ? v1 : v2));
        float on = (v - mu) * rstd * gamma[c] + beta[c];
        o[c] = on;
        __nv_bfloat16 h = __float2bfloat16(on);
        ohi[c] = h;
        olo[c] = __float2bfloat16(on - __bfloat162float(h));
    }
}

// ---------------- generic 384^3 GEMM body ------------------------------------
template <bool HAS_BIAS>
__device__ __forceinline__ void gemm384_body(
    const float* __restrict__ A, const float* __restrict__ Bm,
    const float* __restrict__ bias, float* __restrict__ C) {
    __shared__ float sA[16][64];
    __shared__ float sB[16][64];
    int bm = blockIdx.y * 64, bn = blockIdx.x * 64;
    int t = threadIdx.x;
    int tx = t & 15, ty = t >> 4;
    float acc[4][4] = {};
    for (int k0 = 0; k0 < 384; k0 += 16) {
        {
            int m = t >> 2, f = t & 3;
            float4 av = *(const float4*)(A + (size_t)(bm + m) * 384 + k0 + f * 4);
            sA[f * 4 + 0][m] = av.x; sA[f * 4 + 1][m] = av.y;
            sA[f * 4 + 2][m] = av.z; sA[f * 4 + 3][m] = av.w;
        }
        {
            int kk = t >> 4, n4 = t & 15;
            *(float4*)&sB[kk][n4 * 4] =
                *(const float4*)(Bm + (size_t)(k0 + kk) * 384 + bn + n4 * 4);
        }
        __syncthreads();
        #pragma unroll
        for (int kk = 0; kk < 16; ++kk) {
            float4 a4 = *(const float4*)&sA[kk][ty * 4];
            float4 b4 = *(const float4*)&sB[kk][tx * 4];
            float av[4] = {a4.x, a4.y, a4.z, a4.w};
            float bv[4] = {b4.x, b4.y, b4.z, b4.w};
            #pragma unroll
            for (int i = 0; i < 4; ++i)
                #pragma unroll
                for (int j = 0; j < 4; ++j)
                    acc[i][j] += av[i] * bv[j];
        }
        __syncthreads();
    }
    #pragma unroll
    for (int i = 0; i < 4; ++i)
        #pragma unroll
        for (int j = 0; j < 4; ++j) {
            float v = acc[i][j];
            if (HAS_BIAS) v += bias[bn + tx * 4 + j];
            C[(size_t)(bm + ty * 4 + i) * 384 + bn + tx * 4 + j] = v;
        }
}
__global__ __launch_bounds__(256) void vproj_kernel(const float* __restrict__ wv) {
    gemm384_body<false>(g_xn, wv, nullptr, g_v);
}
__global__ __launch_bounds__(256) void oproj_kernel(const float* __restrict__ wo,
                                                    const float* __restrict__ bo,
                                                    float* __restrict__ out) {
    gemm384_body<true>(g_ctx, wo, bo, out);
}

// ---------------- diagonal dual-GEMM via mma.sync (bf16 hi/lo, K'=1152) ------
// grid (6 mtiles, 192 r), 256 threads = 8 warps (2m x 2n x 2qk).
// Block: 64 stacked rows x 96 cols (quarter) x K'=1152. 3-stage cp.async.
#define STG      15360
#define OFF_AQ   0
#define OFF_AK   3072
#define OFF_BQ   6144
#define OFF_BK   10752

__global__ __launch_bounds__(256, 3) void diag_mma_kernel() {
    int r = blockIdx.y;
    int mtile = blockIdx.x;
    int M = L - r;
    int rows2 = 2 * M;
    int m0 = mtile * 64;
    if (m0 >= rows2) return;

    __shared__ __align__(16) uint8_t sm[3 * STG];
    uint32_t su = smem_u32(sm);
    int tid = threadIdx.x, lane = tid & 31, wid = tid >> 5;
    int wm = wid & 1, wn = (wid >> 1) & 1, qk = wid >> 2;

    auto issue = [&](int ch, int st, int ncol0) {
        int seg = ch / 24;                 // A: 0 hi 1 lo 2 hi ; B: 0 hi 1 hi 2 lo
        int k0 = (ch % 24) * 16;
        const __nv_bfloat16* aBase = (seg == 1) ? g_xn_lo : g_xn_hi;
        uint32_t sbase = su + st * STG;
        #pragma unroll
        for (int it = 0; it < 3; ++it) {
            int idx = tid + it * 256;
            if (idx < 256) {
                int tile = idx >> 7, rem = idx & 127, m = rem >> 1, v = rem & 1;
                uint32_t dst = sbase + tile * OFF_AK + m * 48 + v * 16;
                int g = m0 + m;
                if (g < rows2) {
                    int bb = g >= M;
                    int mm = g - (bb ? M : 0);
                    int xrow = bb * L + (tile == 0 ? r + mm : mm);
                    CP16(dst, aBase + (size_t)xrow * D + k0 + v * 8);
                } else {
                    CP16Z(dst);
                }
            } else if (idx < 640) {
                int j = idx - 256;
                int mat = j >= 192;
                int rem = j - (mat ? 192 : 0);
                int n = rem >> 1, v = rem & 1;
                uint32_t dst = sbase + OFF_BQ + mat * 4608 + n * 48 + v * 16;
                int ridx = mat ? r : (L - 1 - r);
                const __nv_bfloat16* base =
                    mat ? ((seg == 2) ? g_ukt_lo : g_ukt_hi)
                        : ((seg == 2) ? g_uqt_lo : g_uqt_hi);
                CP16(dst, base + ((size_t)ridx * D + ncol0 + n) * D + k0 + v * 8);
            }
        }
    };

    uint32_t offA = qk ? OFF_AK : OFF_AQ;
    uint32_t offB = qk ? OFF_BK : OFF_BQ;
    int arow = (lane & 8) + (lane & 7);
    uint32_t au = (uint32_t)(lane >> 4) * 16;
    int lb = lane & 15;
    int brow = lb & 7;
    uint32_t bu = (uint32_t)(lb >> 3) * 16;

    for (int quarter = 0; quarter < 4; ++quarter) {
        int ncol0 = quarter * 96;
        float acc[2][6][4] = {};

        issue(0, 0, ncol0); CP_COMMIT();
        issue(1, 1, ncol0); CP_COMMIT();

        for (int ch = 0; ch < 72; ++ch) {
            int st = ch - (ch / 3) * 3;
            CP_WAIT1();
            __syncthreads();
            if (ch + 2 < 72) issue(ch + 2, (ch + 2) % 3, ncol0);
            CP_COMMIT();
            uint32_t sb = su + st * STG;
            uint32_t af[2][4];
            #pragma unroll
            for (int band = 0; band < 2; ++band) {
                int rb = wm * 32 + band * 16 + arow;
                ldmx4(af[band], sb + offA + rb * 48 + au);
            }
            #pragma unroll
            for (int nt = 0; nt < 6; ++nt) {
                int n0 = wn * 48 + nt * 8 + brow;
                uint32_t bf[2];
                ldmx2(bf, sb + offB + n0 * 48 + bu);
                #pragma unroll
                for (int band = 0; band < 2; ++band)
                    mma16816(acc[band][nt], af[band], bf);
            }
        }

        // ---- epilogue: exchange K accs via smem, rowwise dot ---------------
        __syncthreads();
        float (*sEx)[97] = (float (*)[97])sm;
        if (qk == 1) {
            #pragma unroll
            for (int band = 0; band < 2; ++band)
                #pragma unroll
                for (int h = 0; h < 2; ++h) {
                    int row = wm * 32 + band * 16 + (lane >> 2) + 8 * h;
                    #pragma unroll
                    for (int nt = 0; nt < 6; ++nt) {
                        int c0 = wn * 48 + nt * 8 + (lane & 3) * 2;
                        sEx[row][c0] = acc[band][nt][2 * h];
                        sEx[row][c0 + 1] = acc[band][nt][2 * h + 1];
                    }
                }
        }
        __syncthreads();
        if (qk == 0) {
            #pragma unroll
            for (int band = 0; band < 2; ++band)
                #pragma unroll
                for (int h = 0; h < 2; ++h) {
                    int row = wm * 32 + band * 16 + (lane >> 2) + 8 * h;
                    float p = 0.f;
                    #pragma unroll
                    for (int nt = 0; nt < 6; ++nt) {
                        int c0 = wn * 48 + nt * 8 + (lane & 3) * 2;
                        p += acc[band][nt][2 * h] * sEx[row][c0]
                           + acc[band][nt][2 * h + 1] * sEx[row][c0 + 1];
                    }
                    p += __shfl_xor_sync(0xffffffffu, p, 1);
                    p += __shfl_xor_sync(0xffffffffu, p, 2);
                    if ((lane & 3) == 0) {
                        int g = m0 + row;
                        if (g < rows2) {
                            int bb = g >= M;
                            int mm = g - (bb ? M : 0);
                            int i = r + mm, j = mm;
                            int head = quarter * 2 + wn;
                            g_dots[((size_t)(bb * H + head) * L + i) * L + j] = p * SCALE;
                        }
                    }
                }
        }
        __syncthreads();
    }
}

// ---------------- softmax + attn @ v -----------------------------------------
__global__ __launch_bounds__(192) void softmax_av_kernel() {
    int i = blockIdx.x, h = blockIdx.y, b = blockIdx.z;
    int t = threadIdx.x;
    const float* drow = g_dots + ((size_t)(b * H + h) * L + i) * L;

    __shared__ float sP[192];
    __shared__ float swork[6];
    __shared__ float smax, ssum;
    __shared__ float sAcc[4][48];

    float val = (t <= i) ? drow[t] : -INFINITY;
    float m = val;
    #pragma unroll
    for (int off = 16; off; off >>= 1)
        m = fmaxf(m, __shfl_xor_sync(0xffffffffu, m, off));
    if ((t & 31) == 0) swork[t >> 5] = m;
    __syncthreads();
    if (t == 0) {
        float mm = swork[0];
        #pragma unroll
        for (int k = 1; k < 6; ++k) mm = fmaxf(mm, swork[k]);
        smax = mm;
    }
    __syncthreads();
    float p = (t <= i) ? expf(val - smax) : 0.f;
    sP[t] = p;
    float s = p;
    #pragma unroll
    for (int off = 16; off; off >>= 1)
        s += __shfl_xor_sync(0xffffffffu, s, off);
    if ((t & 31) == 0) swork[t >> 5] = s;
    __syncthreads();
    if (t == 0) {
        float acc = 0.f;
        #pragma unroll
        for (int k = 0; k < 6; ++k) acc += swork[k];
        ssum = acc;
    }
    __syncthreads();
    float inv = 1.0f / ssum;

    int d = t % 48, q = t / 48;
    float acc = 0.f;
    for (int j = q; j <= i; j += 4)
        acc += sP[j] * g_v[(size_t)(b * L + j) * D + h * DH + d];
    sAcc[q][d] = acc;
    __syncthreads();
    if (t < 48) {
        float o = (sAcc[0][t] + sAcc[1][t] + sAcc[2][t] + sAcc[3][t]) * inv;
        g_ctx[(size_t)(b * L + i) * D + h * DH + t] = o;
    }
}

extern "C" void kernel_launch(void* const* d_in, const int* in_sizes, int n_in,
                              void* d_out, int out_size) {
    const float* x     = (const float*)d_in[0];
    const float* gamma = (const float*)d_in[1];
    const float* beta  = (const float*)d_in[2];
    const float* uq    = (const float*)d_in[3];
    const float* uk    = (const float*)d_in[4];
    const float* wv    = (const float*)d_in[5];
    const float* wo    = (const float*)d_in[6];
    const float* bo    = (const float*)d_in[7];
    float* out = (float*)d_out;
    (void)in_sizes; (void)n_in; (void)out_size;

    // 1) transpose + hi/lo split of u weights
    tconv_kernel<<<dim3(12, 6, 2 * L), dim3(32, 8)>>>(uq, uk);
    // 2) LayerNorm (+ bf16 hi/lo)
    ln_kernel<<<BATCH * L, 128>>>(x, gamma, beta);
    // 3) v = xn @ w_v
    vproj_kernel<<<dim3(6, 6), 256>>>(wv);
    // 4) per-diagonal dual GEMM + per-head dots (mma.sync bf16 hi/lo)
    diag_mma_kernel<<<dim3(6, L), 256>>>();
    // 5) causal softmax + attn @ v
    softmax_av_kernel<<<dim3(L, H, BATCH), 192>>>();
    // 6) out = ctx @ w_o + b_o
    oproj_kernel<<<dim3(6, 6), 256>>>(wo, bo, out);
}

// round 8
// speedup vs baseline: 2.2653x; 1.2353x over previous
#include <cuda_runtime.h>
#include <cuda_bf16.h>
#include <math.h>
#include <stdint.h>

#define BATCH 2
#define L 192
#define D 384
#define H 8
#define DH 48
#define EPS 1e-5f
#define SCALE 0.14433756729740643f   // 1/sqrt(48)

// ---------------- scratch (device globals) ----------------------------------
__device__ __align__(16) float g_xn[BATCH * L * D];
__device__ __align__(16) __nv_bfloat16 g_xn_hi[BATCH * L * D];
__device__ __align__(16) __nv_bfloat16 g_xn_lo[BATCH * L * D];
__device__ __align__(16) float g_v[BATCH * L * D];
__device__ __align__(16) float g_dots[BATCH * H * L * L];
__device__ __align__(16) float g_ctx[BATCH * L * D];
// transposed + hi/lo-split u weights: [r][n][k] K-major bf16
__device__ __align__(16) __nv_bfloat16 g_uqt_hi[L * D * D];
__device__ __align__(16) __nv_bfloat16 g_uqt_lo[L * D * D];
__device__ __align__(16) __nv_bfloat16 g_ukt_hi[L * D * D];
__device__ __align__(16) __nv_bfloat16 g_ukt_lo[L * D * D];

// ---------------- helpers -----------------------------------------------------
__device__ __forceinline__ uint32_t smem_u32(const void* p) {
    uint32_t a;
    asm("{ .reg .u64 t; cvta.to.shared.u64 t, %1; cvt.u32.u64 %0, t; }"
        : "=r"(a) : "l"(p));
    return a;
}
__device__ __forceinline__ void ldmx4(uint32_t* f, uint32_t a) {
    asm volatile("ldmatrix.sync.aligned.m8n8.x4.shared.b16 {%0,%1,%2,%3}, [%4];"
                 : "=r"(f[0]), "=r"(f[1]), "=r"(f[2]), "=r"(f[3]) : "r"(a));
}
__device__ __forceinline__ void mma16816(float* c, const uint32_t* a, const uint32_t* b) {
    asm volatile(
        "mma.sync.aligned.m16n8k16.row.col.f32.bf16.bf16.f32 "
        "{%0,%1,%2,%3}, {%4,%5,%6,%7}, {%8,%9}, {%0,%1,%2,%3};"
        : "+f"(c[0]), "+f"(c[1]), "+f"(c[2]), "+f"(c[3])
        : "r"(a[0]), "r"(a[1]), "r"(a[2]), "r"(a[3]), "r"(b[0]), "r"(b[1]));
}
#define CP16(dst, src) \
    asm volatile("cp.async.cg.shared.global [%0], [%1], 16;" :: "r"(dst), "l"(src))
#define CP16Z(dst) \
    asm volatile("cp.async.cg.shared.global [%0], [%1], 16, 0;" \
                 :: "r"(dst), "l"((const void*)g_xn_hi))
#define CP_COMMIT() asm volatile("cp.async.commit_group;" ::: "memory")
#define CP_WAIT2()  asm volatile("cp.async.wait_group 2;" ::: "memory")

// ---------------- u transpose + hi/lo split ----------------------------------
__global__ void tconv_kernel(const float* __restrict__ uq,
                             const float* __restrict__ uk) {
    int z = blockIdx.z;
    int mat = z / L, r = z % L;
    const float* src = (mat ? uk : uq) + (size_t)r * D * D;
    __nv_bfloat16* dhi = (mat ? g_ukt_hi : g_uqt_hi) + (size_t)r * D * D;
    __nv_bfloat16* dlo = (mat ? g_ukt_lo : g_uqt_lo) + (size_t)r * D * D;
    __shared__ float tile[64][33];
    int k0 = blockIdx.y * 64, n0 = blockIdx.x * 32;
    int tx = threadIdx.x, ty = threadIdx.y;
    #pragma unroll
    for (int i = 0; i < 8; ++i)
        tile[ty + 8 * i][tx] = src[(size_t)(k0 + ty + 8 * i) * D + n0 + tx];
    __syncthreads();
    #pragma unroll
    for (int i = 0; i < 4; ++i) {
        int n = ty + 8 * i;
        float v0 = tile[2 * tx][n], v1 = tile[2 * tx + 1][n];
        __nv_bfloat16 h0 = __float2bfloat16(v0);
        __nv_bfloat16 h1 = __float2bfloat16(v1);
        __nv_bfloat16 l0 = __float2bfloat16(v0 - __bfloat162float(h0));
        __nv_bfloat16 l1 = __float2bfloat16(v1 - __bfloat162float(h1));
        size_t o = (size_t)(n0 + n) * D + k0 + 2 * tx;
        *(__nv_bfloat162*)(dhi + o) = __nv_bfloat162(h0, h1);
        *(__nv_bfloat162*)(dlo + o) = __nv_bfloat162(l0, l1);
    }
}

// ---------------- LayerNorm (+ bf16 hi/lo emit) -------------------------------
__global__ void ln_kernel(const float* __restrict__ x,
                          const float* __restrict__ gamma,
                          const float* __restrict__ beta) {
    int row = blockIdx.x;
    const float* xr = x + (size_t)row * D;
    float* o = g_xn + (size_t)row * D;
    __nv_bfloat16* ohi = g_xn_hi + (size_t)row * D;
    __nv_bfloat16* olo = g_xn_lo + (size_t)row * D;
    int t = threadIdx.x;
    float v0 = xr[t], v1 = xr[t + 128], v2 = xr[t + 256];
    float s = v0 + v1 + v2;
    float sq = v0 * v0 + v1 * v1 + v2 * v2;
    #pragma unroll
    for (int off = 16; off; off >>= 1) {
        s  += __shfl_xor_sync(0xffffffffu, s,  off);
        sq += __shfl_xor_sync(0xffffffffu, sq, off);
    }
    __shared__ float ss[4], ssq[4];
    int w = t >> 5;
    if ((t & 31) == 0) { ss[w] = s; ssq[w] = sq; }
    __syncthreads();
    __shared__ float smu, srstd;
    if (t == 0) {
        float a = ss[0] + ss[1] + ss[2] + ss[3];
        float b2 = ssq[0] + ssq[1] + ssq[2] + ssq[3];
        float mu = a * (1.0f / D);
        float var = b2 * (1.0f / D) - mu * mu;
        smu = mu;
        srstd = rsqrtf(var + EPS);
    }
    __syncthreads();
    float mu = smu, rstd = srstd;
    #pragma unroll
    for (int seg = 0; seg < 3; ++seg) {
        int c = t + seg * 128;
        float v = (seg == 0 ? v0 : (seg == 1 ? v1 : v2));
        float on = (v - mu) * rstd * gamma[c] + beta[c];
        o[c] = on;
        __nv_bfloat16 h = __float2bfloat16(on);
        ohi[c] = h;
        olo[c] = __float2bfloat16(on - __bfloat162float(h));
    }
}

// ---------------- generic 384^3 GEMM body ------------------------------------
template <bool HAS_BIAS>
__device__ __forceinline__ void gemm384_body(
    const float* __restrict__ A, const float* __restrict__ Bm,
    const float* __restrict__ bias, float* __restrict__ C) {
    __shared__ float sA[16][64];
    __shared__ float sB[16][64];
    int bm = blockIdx.y * 64, bn = blockIdx.x * 64;
    int t = threadIdx.x;
    int tx = t & 15, ty = t >> 4;
    float acc[4][4] = {};
    for (int k0 = 0; k0 < 384; k0 += 16) {
        {
            int m = t >> 2, f = t & 3;
            float4 av = *(const float4*)(A + (size_t)(bm + m) * 384 + k0 + f * 4);
            sA[f * 4 + 0][m] = av.x; sA[f * 4 + 1][m] = av.y;
            sA[f * 4 + 2][m] = av.z; sA[f * 4 + 3][m] = av.w;
        }
        {
            int kk = t >> 4, n4 = t & 15;
            *(float4*)&sB[kk][n4 * 4] =
                *(const float4*)(Bm + (size_t)(k0 + kk) * 384 + bn + n4 * 4);
        }
        __syncthreads();
        #pragma unroll
        for (int kk = 0; kk < 16; ++kk) {
            float4 a4 = *(const float4*)&sA[kk][ty * 4];
            float4 b4 = *(const float4*)&sB[kk][tx * 4];
            float av[4] = {a4.x, a4.y, a4.z, a4.w};
            float bv[4] = {b4.x, b4.y, b4.z, b4.w};
            #pragma unroll
            for (int i = 0; i < 4; ++i)
                #pragma unroll
                for (int j = 0; j < 4; ++j)
                    acc[i][j] += av[i] * bv[j];
        }
        __syncthreads();
    }
    #pragma unroll
    for (int i = 0; i < 4; ++i)
        #pragma unroll
        for (int j = 0; j < 4; ++j) {
            float v = acc[i][j];
            if (HAS_BIAS) v += bias[bn + tx * 4 + j];
            C[(size_t)(bm + ty * 4 + i) * 384 + bn + tx * 4 + j] = v;
        }
}
__global__ __launch_bounds__(256) void vproj_kernel(const float* __restrict__ wv) {
    gemm384_body<false>(g_xn, wv, nullptr, g_v);
}
__global__ __launch_bounds__(256) void oproj_kernel(const float* __restrict__ wo,
                                                    const float* __restrict__ bo,
                                                    float* __restrict__ out) {
    gemm384_body<true>(g_ctx, wo, bo, out);
}

// ---------------- diagonal dual-GEMM via mma.sync (bf16 hi/lo, K'=1152) ------
// grid (6 mtiles, 192 r), 256 threads = 8 warps (2m x 2n x 2qk).
// Block: 64 stacked rows x 96 cols (quarter) x K'=1152.
// 4-stage cp.async, 32B-pitch swizzled tiles, 10KB/stage (40KB total).
#define STG      10240
#define OFF_AQ   0
#define OFF_AK   2048
#define OFF_BQ   4096
#define OFF_BK   7168
// swizzled byte offset for (row, 16B-half koff) at 32B pitch
#define SWO(row, koff) ((row) * 32 + ((koff) ^ (((row) & 4) << 2)))

__global__ __launch_bounds__(256, 3) void diag_mma_kernel() {
    int r = blockIdx.y;
    int mtile = blockIdx.x;
    int M = L - r;
    int rows2 = 2 * M;
    int m0 = mtile * 64;
    if (m0 >= rows2) return;

    __shared__ __align__(16) uint8_t sm[4 * STG];
    uint32_t su = smem_u32(sm);
    int tid = threadIdx.x, lane = tid & 31, wid = tid >> 5;
    int wm = wid & 1, wn = (wid >> 1) & 1, qk = wid >> 2;

    auto issue = [&](int ch, int st, int ncol0) {
        int seg = ch / 24;                 // A: 0 hi 1 lo 2 hi ; B: 0 hi 1 hi 2 lo
        int k0 = (ch % 24) * 16;
        const __nv_bfloat16* aBase = (seg == 1) ? g_xn_lo : g_xn_hi;
        uint32_t sbase = su + st * STG;
        #pragma unroll
        for (int it = 0; it < 3; ++it) {
            int idx = tid + it * 256;
            if (idx < 256) {
                int tile = idx >> 7, rem = idx & 127, m = rem >> 1, v = rem & 1;
                uint32_t dst = sbase + tile * OFF_AK + SWO(m, v * 16);
                int g = m0 + m;
                if (g < rows2) {
                    int bb = g >= M;
                    int mm = g - (bb ? M : 0);
                    int xrow = bb * L + (tile == 0 ? r + mm : mm);
                    CP16(dst, aBase + (size_t)xrow * D + k0 + v * 8);
                } else {
                    CP16Z(dst);
                }
            } else if (idx < 640) {
                int j = idx - 256;
                int mat = j >= 192;
                int rem = j - (mat ? 192 : 0);
                int n = rem >> 1, v = rem & 1;
                uint32_t dst = sbase + OFF_BQ + mat * (OFF_BK - OFF_BQ) + SWO(n, v * 16);
                int ridx = mat ? r : (L - 1 - r);
                const __nv_bfloat16* base =
                    mat ? ((seg == 2) ? g_ukt_lo : g_ukt_hi)
                        : ((seg == 2) ? g_uqt_lo : g_uqt_hi);
                CP16(dst, base + ((size_t)ridx * D + ncol0 + n) * D + k0 + v * 8);
            }
        }
    };

    uint32_t offA = qk ? OFF_AK : OFF_AQ;
    uint32_t offB = qk ? OFF_BK : OFF_BQ;
    int arow = (lane & 8) + (lane & 7);             // 0..15
    uint32_t au = (uint32_t)(lane >> 4) * 16;       // k-half for A
    int bcol_base = (lane & 7) + ((lane >> 4) << 3);  // 0..15 within 16-col pair
    uint32_t bko = (uint32_t)(lane & 8) << 1;       // k-half for B

    for (int quarter = 0; quarter < 4; ++quarter) {
        int ncol0 = quarter * 96;
        float acc[2][6][4] = {};

        issue(0, 0, ncol0); CP_COMMIT();
        issue(1, 1, ncol0); CP_COMMIT();
        issue(2, 2, ncol0); CP_COMMIT();

        for (int ch = 0; ch < 72; ++ch) {
            int st = ch & 3;
            CP_WAIT2();
            __syncthreads();
            if (ch + 3 < 72) issue(ch + 3, (ch + 3) & 3, ncol0);
            CP_COMMIT();
            uint32_t sb = su + st * STG;
            uint32_t af[2][4];
            #pragma unroll
            for (int band = 0; band < 2; ++band) {
                int rb = wm * 32 + band * 16 + arow;
                ldmx4(af[band], sb + offA + SWO(rb, au));
            }
            #pragma unroll
            for (int np = 0; np < 3; ++np) {
                int c = wn * 48 + np * 16 + bcol_base;
                uint32_t bf[4];
                ldmx4(bf, sb + offB + SWO(c, bko));
                #pragma unroll
                for (int band = 0; band < 2; ++band) {
                    mma16816(acc[band][2 * np],     af[band], bf);
                    mma16816(acc[band][2 * np + 1], af[band], bf + 2);
                }
            }
        }

        // ---- epilogue: exchange K accs via smem, rowwise dot ---------------
        __syncthreads();
        float (*sEx)[97] = (float (*)[97])sm;
        if (qk == 1) {
            #pragma unroll
            for (int band = 0; band < 2; ++band)
                #pragma unroll
                for (int h = 0; h < 2; ++h) {
                    int row = wm * 32 + band * 16 + (lane >> 2) + 8 * h;
                    #pragma unroll
                    for (int nt = 0; nt < 6; ++nt) {
                        int c0 = wn * 48 + nt * 8 + (lane & 3) * 2;
                        sEx[row][c0] = acc[band][nt][2 * h];
                        sEx[row][c0 + 1] = acc[band][nt][2 * h + 1];
                    }
                }
        }
        __syncthreads();
        if (qk == 0) {
            #pragma unroll
            for (int band = 0; band < 2; ++band)
                #pragma unroll
                for (int h = 0; h < 2; ++h) {
                    int row = wm * 32 + band * 16 + (lane >> 2) + 8 * h;
                    float p = 0.f;
                    #pragma unroll
                    for (int nt = 0; nt < 6; ++nt) {
                        int c0 = wn * 48 + nt * 8 + (lane & 3) * 2;
                        p += acc[band][nt][2 * h] * sEx[row][c0]
                           + acc[band][nt][2 * h + 1] * sEx[row][c0 + 1];
                    }
                    p += __shfl_xor_sync(0xffffffffu, p, 1);
                    p += __shfl_xor_sync(0xffffffffu, p, 2);
                    if ((lane & 3) == 0) {
                        int g = m0 + row;
                        if (g < rows2) {
                            int bb = g >= M;
                            int mm = g - (bb ? M : 0);
                            int i = r + mm, j = mm;
                            int head = quarter * 2 + wn;
                            g_dots[((size_t)(bb * H + head) * L + i) * L + j] = p * SCALE;
                        }
                    }
                }
        }
        __syncthreads();
    }
}

// ---------------- softmax + attn @ v -----------------------------------------
__global__ __launch_bounds__(192) void softmax_av_kernel() {
    int i = blockIdx.x, h = blockIdx.y, b = blockIdx.z;
    int t = threadIdx.x;
    const float* drow = g_dots + ((size_t)(b * H + h) * L + i) * L;

    __shared__ float sP[192];
    __shared__ float swork[6];
    __shared__ float smax, ssum;
    __shared__ float sAcc[4][48];

    float val = (t <= i) ? drow[t] : -INFINITY;
    float m = val;
    #pragma unroll
    for (int off = 16; off; off >>= 1)
        m = fmaxf(m, __shfl_xor_sync(0xffffffffu, m, off));
    if ((t & 31) == 0) swork[t >> 5] = m;
    __syncthreads();
    if (t == 0) {
        float mm = swork[0];
        #pragma unroll
        for (int k = 1; k < 6; ++k) mm = fmaxf(mm, swork[k]);
        smax = mm;
    }
    __syncthreads();
    float p = (t <= i) ? expf(val - smax) : 0.f;
    sP[t] = p;
    float s = p;
    #pragma unroll
    for (int off = 16; off; off >>= 1)
        s += __shfl_xor_sync(0xffffffffu, s, off);
    if ((t & 31) == 0) swork[t >> 5] = s;
    __syncthreads();
    if (t == 0) {
        float acc = 0.f;
        #pragma unroll
        for (int k = 0; k < 6; ++k) acc += swork[k];
        ssum = acc;
    }
    __syncthreads();
    float inv = 1.0f / ssum;

    int d = t % 48, q = t / 48;
    float acc = 0.f;
    for (int j = q; j <= i; j += 4)
        acc += sP[j] * g_v[(size_t)(b * L + j) * D + h * DH + d];
    sAcc[q][d] = acc;
    __syncthreads();
    if (t < 48) {
        float o = (sAcc[0][t] + sAcc[1][t] + sAcc[2][t] + sAcc[3][t]) * inv;
        g_ctx[(size_t)(b * L + i) * D + h * DH + t] = o;
    }
}

extern "C" void kernel_launch(void* const* d_in, const int* in_sizes, int n_in,
                              void* d_out, int out_size) {
    const float* x     = (const float*)d_in[0];
    const float* gamma = (const float*)d_in[1];
    const float* beta  = (const float*)d_in[2];
    const float* uq    = (const float*)d_in[3];
    const float* uk    = (const float*)d_in[4];
    const float* wv    = (const float*)d_in[5];
    const float* wo    = (const float*)d_in[6];
    const float* bo    = (const float*)d_in[7];
    float* out = (float*)d_out;
    (void)in_sizes; (void)n_in; (void)out_size;

    // 1) transpose + hi/lo split of u weights
    tconv_kernel<<<dim3(12, 6, 2 * L), dim3(32, 8)>>>(uq, uk);
    // 2) LayerNorm (+ bf16 hi/lo)
    ln_kernel<<<BATCH * L, 128>>>(x, gamma, beta);
    // 3) v = xn @ w_v
    vproj_kernel<<<dim3(6, 6), 256>>>(wv);
    // 4) per-diagonal dual GEMM + per-head dots (mma.sync bf16 hi/lo)
    diag_mma_kernel<<<dim3(6, L), 256>>>();
    // 5) causal softmax + attn @ v
    softmax_av_kernel<<<dim3(L, H, BATCH), 192>>>();
    // 6) out = ctx @ w_o + b_o
    oproj_kernel<<<dim3(6, 6), 256>>>(wo, bo, out);
}

// round 9
// speedup vs baseline: 2.4836x; 1.0964x over previous
#include <cuda_runtime.h>
#include <cuda_bf16.h>
#include <math.h>
#include <stdint.h>

#define BATCH 2
#define L 192
#define D 384
#define H 8
#define DH 48
#define EPS 1e-5f
#define SCALE 0.14433756729740643f   // 1/sqrt(48)

// ---------------- scratch (device globals) ----------------------------------
__device__ __align__(16) float g_xn[BATCH * L * D];
__device__ __align__(16) __nv_bfloat16 g_xn_hi[BATCH * L * D];
__device__ __align__(16) __nv_bfloat16 g_xn_lo[BATCH * L * D];
__device__ __align__(16) float g_v[BATCH * L * D];
__device__ __align__(16) float g_dots[BATCH * H * L * L];
__device__ __align__(16) float g_ctx[BATCH * L * D];
// transposed + hi/lo-split u weights: [r][n][k] K-major bf16
__device__ __align__(16) __nv_bfloat16 g_uqt_hi[L * D * D];
__device__ __align__(16) __nv_bfloat16 g_uqt_lo[L * D * D];
__device__ __align__(16) __nv_bfloat16 g_ukt_hi[L * D * D];
__device__ __align__(16) __nv_bfloat16 g_ukt_lo[L * D * D];

// ---------------- helpers -----------------------------------------------------
__device__ __forceinline__ uint32_t smem_u32(const void* p) {
    uint32_t a;
    asm("{ .reg .u64 t; cvta.to.shared.u64 t, %1; cvt.u32.u64 %0, t; }"
        : "=r"(a) : "l"(p));
    return a;
}
__device__ __forceinline__ void ldmx4(uint32_t* f, uint32_t a) {
    asm volatile("ldmatrix.sync.aligned.m8n8.x4.shared.b16 {%0,%1,%2,%3}, [%4];"
                 : "=r"(f[0]), "=r"(f[1]), "=r"(f[2]), "=r"(f[3]) : "r"(a));
}
__device__ __forceinline__ void mma16816(float* c, const uint32_t* a, const uint32_t* b) {
    asm volatile(
        "mma.sync.aligned.m16n8k16.row.col.f32.bf16.bf16.f32 "
        "{%0,%1,%2,%3}, {%4,%5,%6,%7}, {%8,%9}, {%0,%1,%2,%3};"
        : "+f"(c[0]), "+f"(c[1]), "+f"(c[2]), "+f"(c[3])
        : "r"(a[0]), "r"(a[1]), "r"(a[2]), "r"(a[3]), "r"(b[0]), "r"(b[1]));
}
#define CP16(dst, src) \
    asm volatile("cp.async.cg.shared.global [%0], [%1], 16;" :: "r"(dst), "l"(src))
#define CP16Z(dst) \
    asm volatile("cp.async.cg.shared.global [%0], [%1], 16, 0;" \
                 :: "r"(dst), "l"((const void*)g_xn_hi))
#define CP_COMMIT() asm volatile("cp.async.commit_group;" ::: "memory")
#define CP_WAIT2()  asm volatile("cp.async.wait_group 2;" ::: "memory")

// ---------------- u transpose + hi/lo split ----------------------------------
__global__ void tconv_kernel(const float* __restrict__ uq,
                             const float* __restrict__ uk) {
    int z = blockIdx.z;
    int mat = z / L, r = z % L;
    const float* src = (mat ? uk : uq) + (size_t)r * D * D;
    __nv_bfloat16* dhi = (mat ? g_ukt_hi : g_uqt_hi) + (size_t)r * D * D;
    __nv_bfloat16* dlo = (mat ? g_ukt_lo : g_uqt_lo) + (size_t)r * D * D;
    __shared__ float tile[64][33];
    int k0 = blockIdx.y * 64, n0 = blockIdx.x * 32;
    int tx = threadIdx.x, ty = threadIdx.y;
    #pragma unroll
    for (int i = 0; i < 8; ++i)
        tile[ty + 8 * i][tx] = src[(size_t)(k0 + ty + 8 * i) * D + n0 + tx];
    __syncthreads();
    #pragma unroll
    for (int i = 0; i < 4; ++i) {
        int n = ty + 8 * i;
        float v0 = tile[2 * tx][n], v1 = tile[2 * tx + 1][n];
        __nv_bfloat16 h0 = __float2bfloat16(v0);
        __nv_bfloat16 h1 = __float2bfloat16(v1);
        __nv_bfloat16 l0 = __float2bfloat16(v0 - __bfloat162float(h0));
        __nv_bfloat16 l1 = __float2bfloat16(v1 - __bfloat162float(h1));
        size_t o = (size_t)(n0 + n) * D + k0 + 2 * tx;
        *(__nv_bfloat162*)(dhi + o) = __nv_bfloat162(h0, h1);
        *(__nv_bfloat162*)(dlo + o) = __nv_bfloat162(l0, l1);
    }
}

// ---------------- LayerNorm (+ bf16 hi/lo emit) -------------------------------
__global__ void ln_kernel(const float* __restrict__ x,
                          const float* __restrict__ gamma,
                          const float* __restrict__ beta) {
    int row = blockIdx.x;
    const float* xr = x + (size_t)row * D;
    float* o = g_xn + (size_t)row * D;
    __nv_bfloat16* ohi = g_xn_hi + (size_t)row * D;
    __nv_bfloat16* olo = g_xn_lo + (size_t)row * D;
    int t = threadIdx.x;
    float v0 = xr[t], v1 = xr[t + 128], v2 = xr[t + 256];
    float s = v0 + v1 + v2;
    float sq = v0 * v0 + v1 * v1 + v2 * v2;
    #pragma unroll
    for (int off = 16; off; off >>= 1) {
        s  += __shfl_xor_sync(0xffffffffu, s,  off);
        sq += __shfl_xor_sync(0xffffffffu, sq, off);
    }
    __shared__ float ss[4], ssq[4];
    int w = t >> 5;
    if ((t & 31) == 0) { ss[w] = s; ssq[w] = sq; }
    __syncthreads();
    __shared__ float smu, srstd;
    if (t == 0) {
        float a = ss[0] + ss[1] + ss[2] + ss[3];
        float b2 = ssq[0] + ssq[1] + ssq[2] + ssq[3];
        float mu = a * (1.0f / D);
        float var = b2 * (1.0f / D) - mu * mu;
        smu = mu;
        srstd = rsqrtf(var + EPS);
    }
    __syncthreads();
    float mu = smu, rstd = srstd;
    #pragma unroll
    for (int seg = 0; seg < 3; ++seg) {
        int c = t + seg * 128;
        float v = (seg == 0 ? v0 : (seg == 1 ? v1 : v2));
        float on = (v - mu) * rstd * gamma[c] + beta[c];
        o[c] = on;
        __nv_bfloat16 h = __float2bfloat16(on);
        ohi[c] = h;
        olo[c] = __float2bfloat16(on - __bfloat162float(h));
    }
}

// ---------------- generic 384^3 GEMM body ------------------------------------
template <bool HAS_BIAS>
__device__ __forceinline__ void gemm384_body(
    const float* __restrict__ A, const float* __restrict__ Bm,
    const float* __restrict__ bias, float* __restrict__ C) {
    __shared__ float sA[16][64];
    __shared__ float sB[16][64];
    int bm = blockIdx.y * 64, bn = blockIdx.x * 64;
    int t = threadIdx.x;
    int tx = t & 15, ty = t >> 4;
    float acc[4][4] = {};
    for (int k0 = 0; k0 < 384; k0 += 16) {
        {
            int m = t >> 2, f = t & 3;
            float4 av = *(const float4*)(A + (size_t)(bm + m) * 384 + k0 + f * 4);
            sA[f * 4 + 0][m] = av.x; sA[f * 4 + 1][m] = av.y;
            sA[f * 4 + 2][m] = av.z; sA[f * 4 + 3][m] = av.w;
        }
        {
            int kk = t >> 4, n4 = t & 15;
            *(float4*)&sB[kk][n4 * 4] =
                *(const float4*)(Bm + (size_t)(k0 + kk) * 384 + bn + n4 * 4);
        }
        __syncthreads();
        #pragma unroll
        for (int kk = 0; kk < 16; ++kk) {
            float4 a4 = *(const float4*)&sA[kk][ty * 4];
            float4 b4 = *(const float4*)&sB[kk][tx * 4];
            float av[4] = {a4.x, a4.y, a4.z, a4.w};
            float bv[4] = {b4.x, b4.y, b4.z, b4.w};
            #pragma unroll
            for (int i = 0; i < 4; ++i)
                #pragma unroll
                for (int j = 0; j < 4; ++j)
                    acc[i][j] += av[i] * bv[j];
        }
        __syncthreads();
    }
    #pragma unroll
    for (int i = 0; i < 4; ++i)
        #pragma unroll
        for (int j = 0; j < 4; ++j) {
            float v = acc[i][j];
            if (HAS_BIAS) v += bias[bn + tx * 4 + j];
            C[(size_t)(bm + ty * 4 + i) * 384 + bn + tx * 4 + j] = v;
        }
}
__global__ __launch_bounds__(256) void vproj_kernel(const float* __restrict__ wv) {
    gemm384_body<false>(g_xn, wv, nullptr, g_v);
}
__global__ __launch_bounds__(256) void oproj_kernel(const float* __restrict__ wo,
                                                    const float* __restrict__ bo,
                                                    float* __restrict__ out) {
    gemm384_body<true>(g_ctx, wo, bo, out);
}

// ---------------- diagonal dual-GEMM via mma.sync (bf16 hi/lo combined) ------
// grid (6 mtiles, 192 r), 256 threads = 8 warps (2m x 2n x 2qk).
// Block: 64 stacked rows x 96 cols (quarter), K=384 in 24 k16 chunks.
// Each chunk holds A(Q,K)x(hi,lo) and B(Q,K)x(hi,lo); 3 term-MMAs per pair.
// 4-stage cp.async, 20KB/stage (80KB dynamic), 32B-pitch swizzled tiles.
#define STG      20480
// A tiles: AQhi 0, AQlo 2048, AKhi 4096, AKlo 6144 ; B tiles: 8192 + t*3072
#define SWO(row, koff) ((row) * 32 + ((koff) ^ (((row) & 4) << 2)))

__global__ __launch_bounds__(256, 2) void diag_mma_kernel() {
    int r = blockIdx.y;
    int mtile = blockIdx.x;
    int M = L - r;
    int rows2 = 2 * M;
    int m0 = mtile * 64;
    if (m0 >= rows2) return;

    extern __shared__ __align__(16) uint8_t smd[];
    uint32_t su = smem_u32(smd);
    int tid = threadIdx.x, lane = tid & 31, wid = tid >> 5;
    int wm = wid & 1, wn = (wid >> 1) & 1, qk = wid >> 2;

    // ---- precomputed cp.async slots (2 A + 3 B per thread) ------------------
    const __nv_bfloat16* aptr[2];
    uint32_t adst[2];
    bool azero[2];
    #pragma unroll
    for (int i = 0; i < 2; ++i) {
        int idx = tid + i * 256;
        int tile = idx >> 7, rem = idx & 127, m = rem >> 1, v = rem & 1;
        adst[i] = tile * 2048 + SWO(m, v * 16);
        int isQ = tile < 2, isLo = tile & 1;
        int g = m0 + m;
        azero[i] = g >= rows2;
        int bb = g >= M;
        int mm = g - (bb ? M : 0);
        if (azero[i]) { bb = 0; mm = 0; }
        int xrow = bb * L + (isQ ? r + mm : mm);
        aptr[i] = (isLo ? g_xn_lo : g_xn_hi) + (size_t)xrow * D + v * 8;
    }
    const __nv_bfloat16* bptr[3];
    uint32_t bdst[3];
    #pragma unroll
    for (int i = 0; i < 3; ++i) {
        int j = tid + i * 256;
        int tile = j / 192, rem = j - tile * 192, n = rem >> 1, v = rem & 1;
        bdst[i] = 8192 + tile * 3072 + SWO(n, v * 16);
        int mat = tile >= 2, isLo = tile & 1;
        int ridx = mat ? r : (L - 1 - r);
        const __nv_bfloat16* base =
            mat ? (isLo ? g_ukt_lo : g_ukt_hi) : (isLo ? g_uqt_lo : g_uqt_hi);
        bptr[i] = base + ((size_t)ridx * D + n) * D + v * 8;
    }

    auto issue = [&](int ch, int st, size_t qoff) {
        uint32_t sb = su + st * STG;
        int k0 = ch * 16;
        #pragma unroll
        for (int i = 0; i < 2; ++i) {
            uint32_t dst = sb + adst[i];
            if (azero[i]) CP16Z(dst);
            else          CP16(dst, aptr[i] + k0);
        }
        #pragma unroll
        for (int i = 0; i < 3; ++i)
            CP16(sb + bdst[i], bptr[i] + qoff + k0);
    };

    uint32_t aoff = qk * 4096;
    uint32_t boff = 8192 + qk * 6144;
    int arow = (lane & 8) + (lane & 7);
    uint32_t au = (uint32_t)(lane >> 4) * 16;
    int bcol_base = (lane & 7) + ((lane >> 4) << 3);
    uint32_t bko = (uint32_t)(lane & 8) << 1;

    for (int quarter = 0; quarter < 4; ++quarter) {
        size_t qoff = (size_t)quarter * 96 * D;
        float acc[2][6][4] = {};

        issue(0, 0, qoff); CP_COMMIT();
        issue(1, 1, qoff); CP_COMMIT();
        issue(2, 2, qoff); CP_COMMIT();

        for (int ch = 0; ch < 24; ++ch) {
            int st = ch & 3;
            CP_WAIT2();
            __syncthreads();
            if (ch + 3 < 24) issue(ch + 3, (ch + 3) & 3, qoff);
            CP_COMMIT();
            uint32_t sb = su + st * STG;
            uint32_t af[2][2][4];
            #pragma unroll
            for (int band = 0; band < 2; ++band) {
                int rb = wm * 32 + band * 16 + arow;
                uint32_t ab = sb + aoff + SWO(rb, au);
                ldmx4(af[band][0], ab);
                ldmx4(af[band][1], ab + 2048);
            }
            #pragma unroll
            for (int np = 0; np < 3; ++np) {
                int c = wn * 48 + np * 16 + bcol_base;
                uint32_t bb_ = sb + boff + SWO(c, bko);
                uint32_t bh[4], bl[4];
                ldmx4(bh, bb_);
                ldmx4(bl, bb_ + 3072);
                #pragma unroll
                for (int band = 0; band < 2; ++band)
                    #pragma unroll
                    for (int sub = 0; sub < 2; ++sub) {
                        float* a4 = acc[band][2 * np + sub];
                        mma16816(a4, af[band][0], bh + 2 * sub);
                        mma16816(a4, af[band][1], bh + 2 * sub);
                        mma16816(a4, af[band][0], bl + 2 * sub);
                    }
            }
        }

        // ---- epilogue: exchange K accs via smem, rowwise dot ---------------
        __syncthreads();
        float (*sEx)[97] = (float (*)[97])smd;
        if (qk == 1) {
            #pragma unroll
            for (int band = 0; band < 2; ++band)
                #pragma unroll
                for (int h = 0; h < 2; ++h) {
                    int row = wm * 32 + band * 16 + (lane >> 2) + 8 * h;
                    #pragma unroll
                    for (int nt = 0; nt < 6; ++nt) {
                        int c0 = wn * 48 + nt * 8 + (lane & 3) * 2;
                        sEx[row][c0] = acc[band][nt][2 * h];
                        sEx[row][c0 + 1] = acc[band][nt][2 * h + 1];
                    }
                }
        }
        __syncthreads();
        if (qk == 0) {
            #pragma unroll
            for (int band = 0; band < 2; ++band)
                #pragma unroll
                for (int h = 0; h < 2; ++h) {
                    int row = wm * 32 + band * 16 + (lane >> 2) + 8 * h;
                    float p = 0.f;
                    #pragma unroll
                    for (int nt = 0; nt < 6; ++nt) {
                        int c0 = wn * 48 + nt * 8 + (lane & 3) * 2;
                        p += acc[band][nt][2 * h] * sEx[row][c0]
                           + acc[band][nt][2 * h + 1] * sEx[row][c0 + 1];
                    }
                    p += __shfl_xor_sync(0xffffffffu, p, 1);
                    p += __shfl_xor_sync(0xffffffffu, p, 2);
                    if ((lane & 3) == 0) {
                        int g = m0 + row;
                        if (g < rows2) {
                            int bb = g >= M;
                            int mm = g - (bb ? M : 0);
                            int i = r + mm, j = mm;
                            int head = quarter * 2 + wn;
                            g_dots[((size_t)(bb * H + head) * L + i) * L + j] = p * SCALE;
                        }
                    }
                }
        }
        __syncthreads();
    }
}

// ---------------- softmax + attn @ v -----------------------------------------
__global__ __launch_bounds__(192) void softmax_av_kernel() {
    int i = blockIdx.x, h = blockIdx.y, b = blockIdx.z;
    int t = threadIdx.x;
    const float* drow = g_dots + ((size_t)(b * H + h) * L + i) * L;

    __shared__ float sP[192];
    __shared__ float swork[6];
    __shared__ float smax, ssum;
    __shared__ float sAcc[4][48];

    float val = (t <= i) ? drow[t] : -INFINITY;
    float m = val;
    #pragma unroll
    for (int off = 16; off; off >>= 1)
        m = fmaxf(m, __shfl_xor_sync(0xffffffffu, m, off));
    if ((t & 31) == 0) swork[t >> 5] = m;
    __syncthreads();
    if (t == 0) {
        float mm = swork[0];
        #pragma unroll
        for (int k = 1; k < 6; ++k) mm = fmaxf(mm, swork[k]);
        smax = mm;
    }
    __syncthreads();
    float p = (t <= i) ? expf(val - smax) : 0.f;
    sP[t] = p;
    float s = p;
    #pragma unroll
    for (int off = 16; off; off >>= 1)
        s += __shfl_xor_sync(0xffffffffu, s, off);
    if ((t & 31) == 0) swork[t >> 5] = s;
    __syncthreads();
    if (t == 0) {
        float acc = 0.f;
        #pragma unroll
        for (int k = 0; k < 6; ++k) acc += swork[k];
        ssum = acc;
    }
    __syncthreads();
    float inv = 1.0f / ssum;

    int d = t % 48, q = t / 48;
    float acc = 0.f;
    for (int j = q; j <= i; j += 4)
        acc += sP[j] * g_v[(size_t)(b * L + j) * D + h * DH + d];
    sAcc[q][d] = acc;
    __syncthreads();
    if (t < 48) {
        float o = (sAcc[0][t] + sAcc[1][t] + sAcc[2][t] + sAcc[3][t]) * inv;
        g_ctx[(size_t)(b * L + i) * D + h * DH + t] = o;
    }
}

extern "C" void kernel_launch(void* const* d_in, const int* in_sizes, int n_in,
                              void* d_out, int out_size) {
    const float* x     = (const float*)d_in[0];
    const float* gamma = (const float*)d_in[1];
    const float* beta  = (const float*)d_in[2];
    const float* uq    = (const float*)d_in[3];
    const float* uk    = (const float*)d_in[4];
    const float* wv    = (const float*)d_in[5];
    const float* wo    = (const float*)d_in[6];
    const float* bo    = (const float*)d_in[7];
    float* out = (float*)d_out;
    (void)in_sizes; (void)n_in; (void)out_size;

    cudaFuncSetAttribute(diag_mma_kernel,
                         cudaFuncAttributeMaxDynamicSharedMemorySize, 4 * STG);

    // 1) transpose + hi/lo split of u weights
    tconv_kernel<<<dim3(12, 6, 2 * L), dim3(32, 8)>>>(uq, uk);
    // 2) LayerNorm (+ bf16 hi/lo)
    ln_kernel<<<BATCH * L, 128>>>(x, gamma, beta);
    // 3) v = xn @ w_v
    vproj_kernel<<<dim3(6, 6), 256>>>(wv);
    // 4) per-diagonal dual GEMM + per-head dots (combined hi/lo mma.sync)
    diag_mma_kernel<<<dim3(6, L), 256, 4 * STG>>>();
    // 5) causal softmax + attn @ v
    softmax_av_kernel<<<dim3(L, H, BATCH), 192>>>();
    // 6) out = ctx @ w_o + b_o
    oproj_kernel<<<dim3(6, 6), 256>>>(wo, bo, out);
}

// round 11
// speedup vs baseline: 3.4124x; 1.3740x over previous
#include <cuda_runtime.h>
#include <cuda_bf16.h>
#include <cuda_fp16.h>
#include <math.h>
#include <stdint.h>

#define BATCH 2
#define L 192
#define D 384
#define H 8
#define DH 48
#define EPS 1e-5f
#define SCALE 0.14433756729740643f   // 1/sqrt(48)

// ---------------- scratch (device globals) ----------------------------------
__device__ __align__(16) float g_xn[BATCH * L * D];
__device__ __align__(16) __half g_xn_hi[BATCH * L * D];
__device__ __align__(16) __half g_xn_lo[BATCH * L * D];
__device__ __align__(16) float g_v[BATCH * L * D];
__device__ __align__(16) float g_dots[BATCH * H * L * L];
__device__ __align__(16) float g_ctx[BATCH * L * D];
// transposed fp16 u weights: [r][n][k] K-major
__device__ __align__(16) __half g_uqt[L * D * D];
__device__ __align__(16) __half g_ukt[L * D * D];

// ---------------- helpers -----------------------------------------------------
__device__ __forceinline__ uint32_t smem_u32(const void* p) {
    uint32_t a;
    asm("{ .reg .u64 t; cvta.to.shared.u64 t, %1; cvt.u32.u64 %0, t; }"
        : "=r"(a) : "l"(p));
    return a;
}
__device__ __forceinline__ void ldmx4(uint32_t* f, uint32_t a) {
    asm volatile("ldmatrix.sync.aligned.m8n8.x4.shared.b16 {%0,%1,%2,%3}, [%4];"
                 : "=r"(f[0]), "=r"(f[1]), "=r"(f[2]), "=r"(f[3]) : "r"(a));
}
__device__ __forceinline__ void mma16816h(float* c, const uint32_t* a, const uint32_t* b) {
    asm volatile(
        "mma.sync.aligned.m16n8k16.row.col.f32.f16.f16.f32 "
        "{%0,%1,%2,%3}, {%4,%5,%6,%7}, {%8,%9}, {%0,%1,%2,%3};"
        : "+f"(c[0]), "+f"(c[1]), "+f"(c[2]), "+f"(c[3])
        : "r"(a[0]), "r"(a[1]), "r"(a[2]), "r"(a[3]), "r"(b[0]), "r"(b[1]));
}
#define CP16(dst, src) \
    asm volatile("cp.async.cg.shared.global [%0], [%1], 16;" :: "r"(dst), "l"(src))
#define CP16Z(dst) \
    asm volatile("cp.async.cg.shared.global [%0], [%1], 16, 0;" \
                 :: "r"(dst), "l"((const void*)g_xn_hi))
#define CP_COMMIT() asm volatile("cp.async.commit_group;" ::: "memory")
#define CP_WAIT2()  asm volatile("cp.async.wait_group 2;" ::: "memory")

// ---------------- u transpose + fp16 convert ----------------------------------
__global__ void tconv_kernel(const float* __restrict__ uq,
                             const float* __restrict__ uk) {
    int z = blockIdx.z;
    int mat = z / L, r = z % L;
    const float* src = (mat ? uk : uq) + (size_t)r * D * D;
    __half* dst = (mat ? g_ukt : g_uqt) + (size_t)r * D * D;
    __shared__ float tile[64][33];
    int k0 = blockIdx.y * 64, n0 = blockIdx.x * 32;
    int tx = threadIdx.x, ty = threadIdx.y;
    #pragma unroll
    for (int i = 0; i < 8; ++i)
        tile[ty + 8 * i][tx] = src[(size_t)(k0 + ty + 8 * i) * D + n0 + tx];
    __syncthreads();
    #pragma unroll
    for (int i = 0; i < 4; ++i) {
        int n = ty + 8 * i;
        float v0 = tile[2 * tx][n], v1 = tile[2 * tx + 1][n];
        size_t o = (size_t)(n0 + n) * D + k0 + 2 * tx;
        *(__half2*)(dst + o) = __floats2half2_rn(v0, v1);
    }
}

// ---------------- LayerNorm (+ fp16 hi/lo emit) -------------------------------
__global__ void ln_kernel(const float* __restrict__ x,
                          const float* __restrict__ gamma,
                          const float* __restrict__ beta) {
    int row = blockIdx.x;
    const float* xr = x + (size_t)row * D;
    float* o = g_xn + (size_t)row * D;
    __half* ohi = g_xn_hi + (size_t)row * D;
    __half* olo = g_xn_lo + (size_t)row * D;
    int t = threadIdx.x;
    float v0 = xr[t], v1 = xr[t + 128], v2 = xr[t + 256];
    float s = v0 + v1 + v2;
    float sq = v0 * v0 + v1 * v1 + v2 * v2;
    #pragma unroll
    for (int off = 16; off; off >>= 1) {
        s  += __shfl_xor_sync(0xffffffffu, s,  off);
        sq += __shfl_xor_sync(0xffffffffu, sq, off);
    }
    __shared__ float ss[4], ssq[4];
    int w = t >> 5;
    if ((t & 31) == 0) { ss[w] = s; ssq[w] = sq; }
    __syncthreads();
    __shared__ float smu, srstd;
    if (t == 0) {
        float a = ss[0] + ss[1] + ss[2] + ss[3];
        float b2 = ssq[0] + ssq[1] + ssq[2] + ssq[3];
        float mu = a * (1.0f / D);
        float var = b2 * (1.0f / D) - mu * mu;
        smu = mu;
        srstd = rsqrtf(var + EPS);
    }
    __syncthreads();
    float mu = smu, rstd = srstd;
    #pragma unroll
    for (int seg = 0; seg < 3; ++seg) {
        int c = t + seg * 128;
        float v = (seg == 0 ? v0 : (seg == 1 ? v1 : v2));
        float on = (v - mu) * rstd * gamma[c] + beta[c];
        o[c] = on;
        __half h = __float2half_rn(on);
        ohi[c] = h;
        olo[c] = __float2half_rn(on - __half2float(h));
    }
}

// ---------------- generic 384^3 GEMM body ------------------------------------
template <bool HAS_BIAS>
__device__ __forceinline__ void gemm384_body(
    const float* __restrict__ A, const float* __restrict__ Bm,
    const float* __restrict__ bias, float* __restrict__ C) {
    __shared__ float sA[16][64];
    __shared__ float sB[16][64];
    int bm = blockIdx.y * 64, bn = blockIdx.x * 64;
    int t = threadIdx.x;
    int tx = t & 15, ty = t >> 4;
    float acc[4][4] = {};
    for (int k0 = 0; k0 < 384; k0 += 16) {
        {
            int m = t >> 2, f = t & 3;
            float4 av = *(const float4*)(A + (size_t)(bm + m) * 384 + k0 + f * 4);
            sA[f * 4 + 0][m] = av.x; sA[f * 4 + 1][m] = av.y;
            sA[f * 4 + 2][m] = av.z; sA[f * 4 + 3][m] = av.w;
        }
        {
            int kk = t >> 4, n4 = t & 15;
            *(float4*)&sB[kk][n4 * 4] =
                *(const float4*)(Bm + (size_t)(k0 + kk) * 384 + bn + n4 * 4);
        }
        __syncthreads();
        #pragma unroll
        for (int kk = 0; kk < 16; ++kk) {
            float4 a4 = *(const float4*)&sA[kk][ty * 4];
            float4 b4 = *(const float4*)&sB[kk][tx * 4];
            float av[4] = {a4.x, a4.y, a4.z, a4.w};
            float bv[4] = {b4.x, b4.y, b4.z, b4.w};
            #pragma unroll
            for (int i = 0; i < 4; ++i)
                #pragma unroll
                for (int j = 0; j < 4; ++j)
                    acc[i][j] += av[i] * bv[j];
        }
        __syncthreads();
    }
    #pragma unroll
    for (int i = 0; i < 4; ++i)
        #pragma unroll
        for (int j = 0; j < 4; ++j) {
            float v = acc[i][j];
            if (HAS_BIAS) v += bias[bn + tx * 4 + j];
            C[(size_t)(bm + ty * 4 + i) * 384 + bn + tx * 4 + j] = v;
        }
}
__global__ __launch_bounds__(256) void vproj_kernel(const float* __restrict__ wv) {
    gemm384_body<false>(g_xn, wv, nullptr, g_v);
}
__global__ __launch_bounds__(256) void oproj_kernel(const float* __restrict__ wo,
                                                    const float* __restrict__ bo,
                                                    float* __restrict__ out) {
    gemm384_body<true>(g_ctx, wo, bo, out);
}

// ---------------- diagonal dual-GEMM via mma.sync (fp16 2-term split) --------
// grid (6 mtiles, 192 r), 256 threads = 8 warps (2m x 2n x 2qk).
// Block: 64 stacked rows x 96 cols (quarter), K=384 in 24 k16 chunks.
// Per chunk: A = (Q,K)x(hi,lo) fp16, B = (Q,K) hi fp16. 2 term-MMAs/pair.
// 4-stage cp.async, 14KB/stage (56KB dynamic), 32B-pitch swizzled tiles.
#define STG      14336
// A tiles: AQhi 0, AQlo 2048, AKhi 4096, AKlo 6144 ; B tiles: 8192 + t*3072
#define SWO(row, koff) ((row) * 32 + ((koff) ^ (((row) & 4) << 2)))

__global__ __launch_bounds__(256, 2) void diag_mma_kernel() {
    int r = blockIdx.y;
    int mtile = blockIdx.x;
    int M = L - r;
    int rows2 = 2 * M;
    int m0 = mtile * 64;
    if (m0 >= rows2) return;

    extern __shared__ __align__(16) uint8_t smd[];
    uint32_t su = smem_u32(smd);
    int tid = threadIdx.x, lane = tid & 31, wid = tid >> 5;
    int wm = wid & 1, wn = (wid >> 1) & 1, qk = wid >> 2;

    // ---- precomputed cp.async slots (2 A + up to 2 B per thread) ------------
    const __half* aptr[2];
    uint32_t adst[2];
    bool azero[2];
    #pragma unroll
    for (int i = 0; i < 2; ++i) {
        int idx = tid + i * 256;
        int tile = idx >> 7, rem = idx & 127, m = rem >> 1, v = rem & 1;
        adst[i] = tile * 2048 + SWO(m, v * 16);
        int isQ = tile < 2, isLo = tile & 1;
        int g = m0 + m;
        azero[i] = g >= rows2;
        int bb = g >= M;
        int mm = g - (bb ? M : 0);
        if (azero[i]) { bb = 0; mm = 0; }
        int xrow = bb * L + (isQ ? r + mm : mm);
        aptr[i] = (isLo ? g_xn_lo : g_xn_hi) + (size_t)xrow * D + v * 8;
    }
    // B: 384 slots (2 tiles x 96 rows x 2 halves); slot0 = tid, slot1 = tid+256 (tid<128)
    const __half* bptr[2];
    uint32_t bdst[2];
    bool bval1 = tid < 128;
    #pragma unroll
    for (int i = 0; i < 2; ++i) {
        int j = tid + i * 256;
        if (j >= 384) j = 0;   // inactive (only when i==1 && tid>=128)
        int tile = j / 192, rem = j - tile * 192, n = rem >> 1, v = rem & 1;
        bdst[i] = 8192 + tile * 3072 + SWO(n, v * 16);
        int ridx = tile ? r : (L - 1 - r);
        const __half* base = tile ? g_ukt : g_uqt;
        bptr[i] = base + ((size_t)ridx * D + n) * D + v * 8;
    }

    auto issue = [&](int ch, int st, size_t qoff) {
        uint32_t sb = su + st * STG;
        int k0 = ch * 16;
        #pragma unroll
        for (int i = 0; i < 2; ++i) {
            uint32_t dst = sb + adst[i];
            if (azero[i]) CP16Z(dst);
            else          CP16(dst, aptr[i] + k0);
        }
        CP16(sb + bdst[0], bptr[0] + qoff + k0);
        if (bval1) CP16(sb + bdst[1], bptr[1] + qoff + k0);
    };

    uint32_t aoff = qk * 4096;
    uint32_t boff = 8192 + qk * 3072;
    int arow = (lane & 8) + (lane & 7);
    uint32_t au = (uint32_t)(lane >> 4) * 16;
    int bcol_base = (lane & 7) + ((lane >> 4) << 3);
    uint32_t bko = (uint32_t)(lane & 8) << 1;

    for (int quarter = 0; quarter < 4; ++quarter) {
        size_t qoff = (size_t)quarter * 96 * D;
        float acc[2][6][4] = {};

        issue(0, 0, qoff); CP_COMMIT();
        issue(1, 1, qoff); CP_COMMIT();
        issue(2, 2, qoff); CP_COMMIT();

        for (int ch = 0; ch < 24; ++ch) {
            int st = ch & 3;
            CP_WAIT2();
            __syncthreads();
            if (ch + 3 < 24) issue(ch + 3, (ch + 3) & 3, qoff);
            CP_COMMIT();
            uint32_t sb = su + st * STG;
            uint32_t af[2][2][4];
            #pragma unroll
            for (int band = 0; band < 2; ++band) {
                int rb = wm * 32 + band * 16 + arow;
                uint32_t ab = sb + aoff + SWO(rb, au);
                ldmx4(af[band][0], ab);           // hi
                ldmx4(af[band][1], ab + 2048);    // lo
            }
            #pragma unroll
            for (int np = 0; np < 3; ++np) {
                int c = wn * 48 + np * 16 + bcol_base;
                uint32_t bh[4];
                ldmx4(bh, sb + boff + SWO(c, bko));
                #pragma unroll
                for (int band = 0; band < 2; ++band)
                    #pragma unroll
                    for (int sub = 0; sub < 2; ++sub) {
                        float* a4 = acc[band][2 * np + sub];
                        mma16816h(a4, af[band][0], bh + 2 * sub);
                        mma16816h(a4, af[band][1], bh + 2 * sub);
                    }
            }
        }

        // ---- epilogue: exchange K accs via smem, rowwise dot ---------------
        __syncthreads();
        float (*sEx)[97] = (float (*)[97])smd;
        if (qk == 1) {
            #pragma unroll
            for (int band = 0; band < 2; ++band)
                #pragma unroll
                for (int h = 0; h < 2; ++h) {
                    int row = wm * 32 + band * 16 + (lane >> 2) + 8 * h;
                    #pragma unroll
                    for (int nt = 0; nt < 6; ++nt) {
                        int c0 = wn * 48 + nt * 8 + (lane & 3) * 2;
                        sEx[row][c0] = acc[band][nt][2 * h];
                        sEx[row][c0 + 1] = acc[band][nt][2 * h + 1];
                    }
                }
        }
        __syncthreads();
        if (qk == 0) {
            #pragma unroll
            for (int band = 0; band < 2; ++band)
                #pragma unroll
                for (int h = 0; h < 2; ++h) {
                    int row = wm * 32 + band * 16 + (lane >> 2) + 8 * h;
                    float p = 0.f;
                    #pragma unroll
                    for (int nt = 0; nt < 6; ++nt) {
                        int c0 = wn * 48 + nt * 8 + (lane & 3) * 2;
                        p += acc[band][nt][2 * h] * sEx[row][c0]
                           + acc[band][nt][2 * h + 1] * sEx[row][c0 + 1];
                    }
                    p += __shfl_xor_sync(0xffffffffu, p, 1);
                    p += __shfl_xor_sync(0xffffffffu, p, 2);
                    if ((lane & 3) == 0) {
                        int g = m0 + row;
                        if (g < rows2) {
                            int bb = g >= M;
                            int mm = g - (bb ? M : 0);
                            int i = r + mm, j = mm;
                            int head = quarter * 2 + wn;
                            g_dots[((size_t)(bb * H + head) * L + i) * L + j] = p * SCALE;
                        }
                    }
                }
        }
        __syncthreads();
    }
}

// ---------------- softmax + attn @ v -----------------------------------------
__global__ __launch_bounds__(192) void softmax_av_kernel() {
    int i = blockIdx.x, h = blockIdx.y, b = blockIdx.z;
    int t = threadIdx.x;
    const float* drow = g_dots + ((size_t)(b * H + h) * L + i) * L;

    __shared__ float sP[192];
    __shared__ float swork[6];
    __shared__ float smax, ssum;
    __shared__ float sAcc[4][48];

    float val = (t <= i) ? drow[t] : -INFINITY;
    float m = val;
    #pragma unroll
    for (int off = 16; off; off >>= 1)
        m = fmaxf(m, __shfl_xor_sync(0xffffffffu, m, off));
    if ((t & 31) == 0) swork[t >> 5] = m;
    __syncthreads();
    if (t == 0) {
        float mm = swork[0];
        #pragma unroll
        for (int k = 1; k < 6; ++k) mm = fmaxf(mm, swork[k]);
        smax = mm;
    }
    __syncthreads();
    float p = (t <= i) ? expf(val - smax) : 0.f;
    sP[t] = p;
    float s = p;
    #pragma unroll
    for (int off = 16; off; off >>= 1)
        s += __shfl_xor_sync(0xffffffffu, s, off);
    if ((t & 31) == 0) swork[t >> 5] = s;
    __syncthreads();
    if (t == 0) {
        float acc = 0.f;
        #pragma unroll
        for (int k = 0; k < 6; ++k) acc += swork[k];
        ssum = acc;
    }
    __syncthreads();
    float inv = 1.0f / ssum;

    int d = t % 48, q = t / 48;
    float acc = 0.f;
    for (int j = q; j <= i; j += 4)
        acc += sP[j] * g_v[(size_t)(b * L + j) * D + h * DH + d];
    sAcc[q][d] = acc;
    __syncthreads();
    if (t < 48) {
        float o = (sAcc[0][t] + sAcc[1][t] + sAcc[2][t] + sAcc[3][t]) * inv;
        g_ctx[(size_t)(b * L + i) * D + h * DH + t] = o;
    }
}

extern "C" void kernel_launch(void* const* d_in, const int* in_sizes, int n_in,
                              void* d_out, int out_size) {
    const float* x     = (const float*)d_in[0];
    const float* gamma = (const float*)d_in[1];
    const float* beta  = (const float*)d_in[2];
    const float* uq    = (const float*)d_in[3];
    const float* uk    = (const float*)d_in[4];
    const float* wv    = (const float*)d_in[5];
    const float* wo    = (const float*)d_in[6];
    const float* bo    = (const float*)d_in[7];
    float* out = (float*)d_out;
    (void)in_sizes; (void)n_in; (void)out_size;

    cudaFuncSetAttribute(diag_mma_kernel,
                         cudaFuncAttributeMaxDynamicSharedMemorySize, 4 * STG);

    // 1) transpose + fp16 convert of u weights
    tconv_kernel<<<dim3(12, 6, 2 * L), dim3(32, 8)>>>(uq, uk);
    // 2) LayerNorm (+ fp16 hi/lo)
    ln_kernel<<<BATCH * L, 128>>>(x, gamma, beta);
    // 3) v = xn @ w_v
    vproj_kernel<<<dim3(6, 6), 256>>>(wv);
    // 4) per-diagonal dual GEMM + per-head dots (fp16 2-term mma.sync)
    diag_mma_kernel<<<dim3(6, L), 256, 4 * STG>>>();
    // 5) causal softmax + attn @ v
    softmax_av_kernel<<<dim3(L, H, BATCH), 192>>>();
    // 6) out = ctx @ w_o + b_o
    oproj_kernel<<<dim3(6, 6), 256>>>(wo, bo, out);
}